// round 13
// baseline (speedup 1.0000x reference)
#include <cuda_runtime.h>
#include <cuda_bf16.h>
#include <cuda_fp16.h>
#include <mma.h>
#include <math.h>
#include <stdint.h>

using namespace nvcuda;

// Shapes (fixed by the problem)
#define B_ 4
#define L_ 1024
#define D_ 1024
#define NS_ 16
#define R_ 64
#define E_ 96          // R + 2N
#define F_ 4096        // 4*D
#define ML_ (B_ * L_)  // 4096

// ---------------------------------------------------------------------------
// Scratch (no allocations allowed -> __device__ globals)
// ---------------------------------------------------------------------------
__device__ float g_h0[(size_t)ML_ * D_];     // softplus(ln1(x))
__device__ float g_dbc[(size_t)ML_ * E_];    // h0 @ W_dbc^T
__device__ float g_delta[(size_t)ML_ * D_];  // softplus(dlr @ W_dt^T + b_dt)
__device__ float g_h[(size_t)ML_ * D_];      // h0 + ssm(h0)

// bf16 hi/lo split (dbc path only — precision-sensitive)
__device__ __nv_bfloat16 g_h0h[(size_t)ML_ * D_];
__device__ __nv_bfloat16 g_h0l[(size_t)ML_ * D_];
__device__ __nv_bfloat16 g_wdbh[(size_t)E_ * D_];
__device__ __nv_bfloat16 g_wdbl[(size_t)E_ * D_];

// fp16 single operands for the two big GEMMs
__device__ __half g_m0f[(size_t)ML_ * D_];
__device__ __half g_fcf[(size_t)ML_ * F_];
__device__ __half g_wfcf[(size_t)F_ * D_];
__device__ __half g_wprf[(size_t)D_ * F_];

// ---------------------------------------------------------------------------
// Activations
// ---------------------------------------------------------------------------
__device__ __forceinline__ float softplus_f(float v) {
    return fmaxf(v, 0.0f) + log1pf(__expf(-fabsf(v)));
}
__device__ __forceinline__ float gelu_f(float v) {
    const float c = 0.7978845608028654f;
    float v3 = v * v * v;
    return 0.5f * v * (1.0f + tanhf(c * (v + 0.044715f * v3)));
}

// ---------------------------------------------------------------------------
// PTX helpers
// ---------------------------------------------------------------------------
__device__ __forceinline__ uint32_t smem_u32(const void* p) {
    uint32_t a;
    asm("{ .reg .u64 t; cvta.to.shared.u64 t, %1; cvt.u32.u64 %0, t; }"
        : "=r"(a) : "l"(p));
    return a;
}
__device__ __forceinline__ void cp_async8(uint32_t dst, const void* src) {
    asm volatile("cp.async.ca.shared.global [%0], [%1], 8;\n"
                 :: "r"(dst), "l"(src));
}
__device__ __forceinline__ void cp_async16(uint32_t dst, const void* src) {
    asm volatile("cp.async.cg.shared.global [%0], [%1], 16;\n"
                 :: "r"(dst), "l"(src));
}
__device__ __forceinline__ void cp_commit() {
    asm volatile("cp.async.commit_group;\n" ::: "memory");
}
template <int N>
__device__ __forceinline__ void cp_wait() {
    asm volatile("cp.async.wait_group %0;\n" :: "n"(N) : "memory");
}

// ---------------------------------------------------------------------------
// Big HMMA fp16 GEMM v2: CTA tile 256(M) x 128(N), BK=64, 8 warps (4x2),
// warp tile 64x64, double-buffered 16B cp.async.
// EPI==1: C = gelu(acc) -> fp16 Ch.   EPI==2: C = acc + addv -> fp32 Cf.
// ---------------------------------------------------------------------------
#define HPAD 72                       // halves per row (64 + 8); 144B stride
#define HA_B (256 * HPAD * 2)         // 36864 bytes A tile
#define HB_B (128 * HPAD * 2)         // 18432 bytes B tile
#define HSTG_B (HA_B + HB_B)          // 55296 bytes per stage
#define HSMEM_TOTAL (2 * HSTG_B)      // 110592 bytes (>= 64KB epilogue half)

template <int EPI>
__global__ __launch_bounds__(256) void gemm_hmma_kernel(
    const __half* __restrict__ A, const __half* __restrict__ Bm, int K,
    __half* __restrict__ Ch, float* __restrict__ Cf,
    const float* __restrict__ addv, int ldc) {
    extern __shared__ char dsm[];
    int tid = threadIdx.x;
    int wid = tid >> 5;
    int wm = wid >> 1;       // 0..3 -> rows [wm*64, +64)
    int wn = wid & 1;        // 0..1 -> cols [wn*64, +64)
    int bm = blockIdx.y * 256;
    int bn = blockIdx.x * 128;

    wmma::fragment<wmma::accumulator, 16, 16, 16, float> acc[4][4];
#pragma unroll
    for (int i = 0; i < 4; i++)
#pragma unroll
        for (int j = 0; j < 4; j++) wmma::fill_fragment(acc[i][j], 0.0f);

    auto load_chunk = [&](int st, int kc) {
        uint32_t sb = smem_u32(dsm) + st * HSTG_B;
        int k0 = kc * 64;
        // A: 256 rows x 8 groups of 16B  = 2048 slots
#pragma unroll
        for (int j = 0; j < 8; j++) {
            int idx = tid + j * 256;
            int r = idx >> 3;
            int g = idx & 7;
            cp_async16(sb + (uint32_t)(r * (HPAD * 2) + g * 16),
                       A + (size_t)(bm + r) * K + k0 + g * 8);
        }
        // B: 128 rows x 8 groups = 1024 slots
#pragma unroll
        for (int j = 0; j < 4; j++) {
            int idx = tid + j * 256;
            int r = idx >> 3;
            int g = idx & 7;
            cp_async16(sb + HA_B + (uint32_t)(r * (HPAD * 2) + g * 16),
                       Bm + (size_t)(bn + r) * K + k0 + g * 8);
        }
    };

    const int NC = K / 64;
    load_chunk(0, 0);
    cp_commit();

    for (int kc = 0; kc < NC; kc++) {
        int st = kc & 1;
        if (kc + 1 < NC) {
            load_chunk(st ^ 1, kc + 1);
            cp_commit();
            cp_wait<1>();
        } else {
            cp_wait<0>();
        }
        __syncthreads();

        const __half* sA = (const __half*)(dsm + st * HSTG_B);
        const __half* sB = (const __half*)(dsm + st * HSTG_B + HA_B);

#pragma unroll
        for (int kk = 0; kk < 64; kk += 16) {
            wmma::fragment<wmma::matrix_a, 16, 16, 16, __half,
                           wmma::row_major> fa[4];
#pragma unroll
            for (int i = 0; i < 4; i++)
                wmma::load_matrix_sync(fa[i],
                                       sA + (wm * 64 + i * 16) * HPAD + kk,
                                       HPAD);
#pragma unroll
            for (int j = 0; j < 4; j++) {
                wmma::fragment<wmma::matrix_b, 16, 16, 16, __half,
                               wmma::col_major> fb;
                wmma::load_matrix_sync(fb,
                                       sB + (wn * 64 + j * 16) * HPAD + kk,
                                       HPAD);
#pragma unroll
                for (int i = 0; i < 4; i++)
                    wmma::mma_sync(acc[i][j], fa[i], fb, acc[i][j]);
            }
        }
        __syncthreads();
    }

    // Epilogue: two 128-row halves through a 128x128 fp32 smem staging tile.
    float* sC = (float*)dsm;
#pragma unroll
    for (int half = 0; half < 2; half++) {
        if ((wm >> 1) == half) {
            int lr = (wm & 1) * 64;
#pragma unroll
            for (int i = 0; i < 4; i++)
#pragma unroll
                for (int j = 0; j < 4; j++)
                    wmma::store_matrix_sync(sC + (lr + i * 16) * 128 +
                                                (wn * 64 + j * 16),
                                            acc[i][j], 128,
                                            wmma::mem_row_major);
        }
        __syncthreads();

#pragma unroll
        for (int it = 0; it < 16; it++) {
            int idx = tid + it * 256;
            int r = idx >> 5;
            int c4 = idx & 31;
            float4 v = ((const float4*)(sC + r * 128))[c4];
            size_t row = bm + half * 128 + r;
            size_t col = bn + c4 * 4;
            if (EPI == 1) {
                __half o[4];
                o[0] = __float2half(gelu_f(v.x));
                o[1] = __float2half(gelu_f(v.y));
                o[2] = __float2half(gelu_f(v.z));
                o[3] = __float2half(gelu_f(v.w));
                *(uint2*)(Ch + row * ldc + col) = *(uint2*)o;
            } else {
                const float4 av = *(const float4*)(addv + row * ldc + col);
                *(float4*)(Cf + row * ldc + col) =
                    make_float4(v.x + av.x, v.y + av.y, v.z + av.z,
                                v.w + av.w);
            }
        }
        __syncthreads();
    }
}

// ---------------------------------------------------------------------------
// Small-N WMMA GEMM for dbc (bf16 3-term, precision-sensitive path unchanged)
// ---------------------------------------------------------------------------
#define SPAD 36
#define SA_B (64 * SPAD * 2)
#define SB_B (96 * SPAD * 2)
#define SSTG_B (2 * SA_B + 2 * SB_B)
#define SSMEM_TOTAL (2 * SSTG_B)

__global__ __launch_bounds__(128) void gemm_wmma_dbc_kernel(
    const __nv_bfloat16* __restrict__ Ah, const __nv_bfloat16* __restrict__ Al,
    const __nv_bfloat16* __restrict__ Bh, const __nv_bfloat16* __restrict__ Bl,
    float* __restrict__ C) {
    extern __shared__ char dsm[];
    int tid = threadIdx.x;
    int wid = tid >> 5;
    int bm = blockIdx.x * 64;
    const int K = D_;

    wmma::fragment<wmma::accumulator, 16, 16, 16, float> acc[6];
#pragma unroll
    for (int j = 0; j < 6; j++) wmma::fill_fragment(acc[j], 0.0f);

    auto load_chunk = [&](int st, int kc) {
        uint32_t sb = smem_u32(dsm) + st * SSTG_B;
        int k0 = kc * 32;
#pragma unroll
        for (int j = 0; j < 4; j++) {
            int idx = tid + j * 128;
            int r = idx >> 3, cg = idx & 7;
            uint32_t so = (uint32_t)(r * (SPAD * 2) + cg * 8);
            size_t ao = (size_t)(bm + r) * K + k0 + cg * 4;
            cp_async8(sb + so, Ah + ao);
            cp_async8(sb + SA_B + so, Al + ao);
        }
#pragma unroll
        for (int j = 0; j < 6; j++) {
            int idx = tid + j * 128;
            int r = idx >> 3, cg = idx & 7;
            uint32_t so = (uint32_t)(r * (SPAD * 2) + cg * 8);
            size_t bo = (size_t)r * K + k0 + cg * 4;
            cp_async8(sb + 2 * SA_B + so, Bh + bo);
            cp_async8(sb + 2 * SA_B + SB_B + so, Bl + bo);
        }
    };

    const int NC = K / 32;
    load_chunk(0, 0);
    cp_commit();

    for (int kc = 0; kc < NC; kc++) {
        int st = kc & 1;
        if (kc + 1 < NC) {
            load_chunk(st ^ 1, kc + 1);
            cp_commit();
            cp_wait<1>();
        } else {
            cp_wait<0>();
        }
        __syncthreads();

        const __nv_bfloat16* sAh = (const __nv_bfloat16*)(dsm + st * SSTG_B);
        const __nv_bfloat16* sAl =
            (const __nv_bfloat16*)(dsm + st * SSTG_B + SA_B);
        const __nv_bfloat16* sBh =
            (const __nv_bfloat16*)(dsm + st * SSTG_B + 2 * SA_B);
        const __nv_bfloat16* sBl =
            (const __nv_bfloat16*)(dsm + st * SSTG_B + 2 * SA_B + SB_B);

#pragma unroll
        for (int kk = 0; kk < 32; kk += 16) {
            wmma::fragment<wmma::matrix_a, 16, 16, 16, __nv_bfloat16,
                           wmma::row_major> fah, fal;
            wmma::fragment<wmma::matrix_b, 16, 16, 16, __nv_bfloat16,
                           wmma::col_major> fbh[6], fbl[6];
            int r0 = wid * 16;
            wmma::load_matrix_sync(fah, sAh + r0 * SPAD + kk, SPAD);
            wmma::load_matrix_sync(fal, sAl + r0 * SPAD + kk, SPAD);
#pragma unroll
            for (int j = 0; j < 6; j++) {
                wmma::load_matrix_sync(fbh[j], sBh + j * 16 * SPAD + kk, SPAD);
                wmma::load_matrix_sync(fbl[j], sBl + j * 16 * SPAD + kk, SPAD);
            }
#pragma unroll
            for (int j = 0; j < 6; j++) {
                wmma::mma_sync(acc[j], fah, fbh[j], acc[j]);
                wmma::mma_sync(acc[j], fal, fbh[j], acc[j]);
                wmma::mma_sync(acc[j], fah, fbl[j], acc[j]);
            }
        }
        __syncthreads();
    }

    float* sC = (float*)dsm;
#pragma unroll
    for (int j = 0; j < 6; j++)
        wmma::store_matrix_sync(sC + (wid * 16) * 96 + j * 16, acc[j], 96,
                                wmma::mem_row_major);
    __syncthreads();

#pragma unroll
    for (int it = 0; it < 12; it++) {
        int idx = tid + it * 128;
        int r = idx / 24;
        int c4 = idx % 24;
        float4 v = ((const float4*)sC)[r * 24 + c4];
        *(float4*)(C + (size_t)(bm + r) * E_ + c4 * 4) = v;
    }
}

// ---------------------------------------------------------------------------
// fp32 -> fp16 converter (weights for the big GEMMs)
// ---------------------------------------------------------------------------
__global__ __launch_bounds__(256) void hconv_kernel(const float* __restrict__ w,
                                                    __half* __restrict__ o,
                                                    int n4) {
    int i = blockIdx.x * blockDim.x + threadIdx.x;
    if (i >= n4) return;
    float4 v = ((const float4*)w)[i];
    __half h[4] = {__float2half(v.x), __float2half(v.y), __float2half(v.z),
                   __float2half(v.w)};
    ((uint2*)o)[i] = *(uint2*)h;
}

// ---------------------------------------------------------------------------
// ln1 fused: blocks [0, ML_) do softplus(ln(x)) -> fp32 + bf16 hi/lo;
// blocks [ML_, ML_+96) split W_dbc fp32 -> bf16 hi/lo.
// ---------------------------------------------------------------------------
__global__ __launch_bounds__(256) void ln1_fused_kernel(
    const float* __restrict__ x, const float* __restrict__ w,
    const float* __restrict__ W_dbc,
    float* __restrict__ out, __nv_bfloat16* __restrict__ oh,
    __nv_bfloat16* __restrict__ ol,
    __nv_bfloat16* __restrict__ wdh, __nv_bfloat16* __restrict__ wdl) {
    __shared__ float red[8];
    if (blockIdx.x >= ML_) {
        int i = (blockIdx.x - ML_) * 256 + threadIdx.x;  // < 24576 = E_*D_/4
        float4 v = ((const float4*)W_dbc)[i];
        float vv[4] = {v.x, v.y, v.z, v.w};
        __nv_bfloat16 h[4], l[4];
#pragma unroll
        for (int j = 0; j < 4; j++) {
            h[j] = __float2bfloat16(vv[j]);
            l[j] = __float2bfloat16(vv[j] - __bfloat162float(h[j]));
        }
        ((uint2*)wdh)[i] = *(uint2*)h;
        ((uint2*)wdl)[i] = *(uint2*)l;
        return;
    }

    int row = blockIdx.x;
    int t = threadIdx.x;
    const float4* xr = (const float4*)(x + (size_t)row * D_);
    float4 v = xr[t];

    float s = v.x + v.y + v.z + v.w;
#pragma unroll
    for (int m = 16; m > 0; m >>= 1) s += __shfl_xor_sync(0xffffffffu, s, m);
    if ((t & 31) == 0) red[t >> 5] = s;
    __syncthreads();
    float tot = 0.0f;
#pragma unroll
    for (int i = 0; i < 8; i++) tot += red[i];
    float mu = tot * (1.0f / D_);

    float cx = v.x - mu, cy = v.y - mu, cz = v.z - mu, cw = v.w - mu;
    float s2 = cx * cx + cy * cy + cz * cz + cw * cw;
#pragma unroll
    for (int m = 16; m > 0; m >>= 1) s2 += __shfl_xor_sync(0xffffffffu, s2, m);
    __syncthreads();
    if ((t & 31) == 0) red[t >> 5] = s2;
    __syncthreads();
    float tot2 = 0.0f;
#pragma unroll
    for (int i = 0; i < 8; i++) tot2 += red[i];
    float rs = rsqrtf(tot2 * (1.0f / D_) + 1e-5f);

    float4 wv = ((const float4*)w)[t];
    float o[4];
    o[0] = softplus_f(cx * rs * wv.x);
    o[1] = softplus_f(cy * rs * wv.y);
    o[2] = softplus_f(cz * rs * wv.z);
    o[3] = softplus_f(cw * rs * wv.w);
    ((float4*)(out + (size_t)row * D_))[t] = make_float4(o[0], o[1], o[2], o[3]);

    __nv_bfloat16 h[4], l[4];
#pragma unroll
    for (int j = 0; j < 4; j++) {
        h[j] = __float2bfloat16(o[j]);
        l[j] = __float2bfloat16(o[j] - __bfloat162float(h[j]));
    }
    ((uint2*)(oh + (size_t)row * D_))[t] = *(uint2*)h;
    ((uint2*)(ol + (size_t)row * D_))[t] = *(uint2*)l;
}

// ---------------------------------------------------------------------------
// ln2: ln(h) -> fp16 single
// ---------------------------------------------------------------------------
__global__ __launch_bounds__(256) void ln2_kernel(const float* __restrict__ x,
                                                  const float* __restrict__ w,
                                                  __half* __restrict__ o16) {
    int row = blockIdx.x;
    int t = threadIdx.x;
    __shared__ float red[8];

    const float4* xr = (const float4*)(x + (size_t)row * D_);
    float4 v = xr[t];

    float s = v.x + v.y + v.z + v.w;
#pragma unroll
    for (int m = 16; m > 0; m >>= 1) s += __shfl_xor_sync(0xffffffffu, s, m);
    if ((t & 31) == 0) red[t >> 5] = s;
    __syncthreads();
    float tot = 0.0f;
#pragma unroll
    for (int i = 0; i < 8; i++) tot += red[i];
    float mu = tot * (1.0f / D_);

    float cx = v.x - mu, cy = v.y - mu, cz = v.z - mu, cw = v.w - mu;
    float s2 = cx * cx + cy * cy + cz * cz + cw * cw;
#pragma unroll
    for (int m = 16; m > 0; m >>= 1) s2 += __shfl_xor_sync(0xffffffffu, s2, m);
    __syncthreads();
    if ((t & 31) == 0) red[t >> 5] = s2;
    __syncthreads();
    float tot2 = 0.0f;
#pragma unroll
    for (int i = 0; i < 8; i++) tot2 += red[i];
    float rs = rsqrtf(tot2 * (1.0f / D_) + 1e-5f);

    float4 wv = ((const float4*)w)[t];
    __half h[4];
    h[0] = __float2half(cx * rs * wv.x);
    h[1] = __float2half(cy * rs * wv.y);
    h[2] = __float2half(cz * rs * wv.z);
    h[3] = __float2half(cw * rs * wv.w);
    ((uint2*)(o16 + (size_t)row * D_))[t] = *(uint2*)h;
}

// ---------------------------------------------------------------------------
// SIMT fp32 GEMM (delta GEMM): C = softplus(A @ B^T + bias)
// ---------------------------------------------------------------------------
#define TBM 128
#define TBN 128
#define TBK 8

template <int ACT, bool HAS_BIAS>
__global__ __launch_bounds__(256) void gemm_kernel(
    const float* __restrict__ A, int lda,
    const float* __restrict__ Bm, int ldb,
    const float* __restrict__ bias,
    float* __restrict__ C, int ldc,
    int M, int N, int K) {
    __shared__ float As[TBK][TBM];
    __shared__ float Bs[TBK][TBN];

    int tid = threadIdx.x;
    int bm = blockIdx.y * TBM;
    int bn = blockIdx.x * TBN;
    int tx = tid & 15;
    int ty = tid >> 4;

    float acc[8][8];
#pragma unroll
    for (int i = 0; i < 8; i++)
#pragma unroll
        for (int j = 0; j < 8; j++) acc[i][j] = 0.0f;

    int trow = tid >> 1;
    int tq = (tid & 1) * 4;
    const float* Aptr = A + (size_t)(bm + trow) * lda + tq;
    bool bvalid = (bn + trow) < N;
    const float* Bptr = Bm + (size_t)(bn + trow) * ldb + tq;

    for (int k0 = 0; k0 < K; k0 += TBK) {
        float4 av = *(const float4*)(Aptr + k0);
        float4 bv = bvalid ? *(const float4*)(Bptr + k0)
                           : make_float4(0.f, 0.f, 0.f, 0.f);
        As[tq + 0][trow] = av.x; As[tq + 1][trow] = av.y;
        As[tq + 2][trow] = av.z; As[tq + 3][trow] = av.w;
        Bs[tq + 0][trow] = bv.x; Bs[tq + 1][trow] = bv.y;
        Bs[tq + 2][trow] = bv.z; Bs[tq + 3][trow] = bv.w;
        __syncthreads();
#pragma unroll
        for (int kk = 0; kk < TBK; kk++) {
            float ra[8], rb[8];
            *(float4*)&ra[0] = *(const float4*)&As[kk][ty * 4];
            *(float4*)&ra[4] = *(const float4*)&As[kk][64 + ty * 4];
            *(float4*)&rb[0] = *(const float4*)&Bs[kk][tx * 4];
            *(float4*)&rb[4] = *(const float4*)&Bs[kk][64 + tx * 4];
#pragma unroll
            for (int i = 0; i < 8; i++)
#pragma unroll
                for (int j = 0; j < 8; j++)
                    acc[i][j] = fmaf(ra[i], rb[j], acc[i][j]);
        }
        __syncthreads();
    }

    int rows[8], cols[8];
#pragma unroll
    for (int i = 0; i < 4; i++) {
        rows[i] = bm + ty * 4 + i;
        rows[i + 4] = bm + 64 + ty * 4 + i;
        cols[i] = bn + tx * 4 + i;
        cols[i + 4] = bn + 64 + tx * 4 + i;
    }
#pragma unroll
    for (int i = 0; i < 8; i++) {
#pragma unroll
        for (int j = 0; j < 8; j++) {
            int gc = cols[j];
            if (gc >= N) continue;
            float v = acc[i][j];
            if (HAS_BIAS) v += bias[gc];
            if (ACT == 1) v = softplus_f(v);
            C[(size_t)rows[i] * ldc + gc] = v;
        }
    }
}

// ---------------------------------------------------------------------------
// Selective scan v3: block-local chunked parallel scan (unchanged).
// ---------------------------------------------------------------------------
#define NCH 16
#define CHL 64
#define SUBL 32

#define SC3_BC 0
#define SC3_PA 65536
#define SC3_ST 98304
#define SC3_SMEM 131072

__global__ __launch_bounds__(512) void scan3_kernel(
    const float* __restrict__ h0, const float* __restrict__ delta,
    const float* __restrict__ dbc, const float* __restrict__ A_log,
    const float* __restrict__ Dp, float* __restrict__ hout) {
    extern __shared__ char dsm[];
    float* sBC = (float*)(dsm + SC3_BC);
    float* sPA = (float*)(dsm + SC3_PA);
    float* sST = (float*)(dsm + SC3_ST);

    int tid = threadIdx.x;
    int lane = tid & 31;
    int w = tid >> 5;
    int d = blockIdx.x * 32 + lane;
    int b = blockIdx.y;

    float negA0 = -__expf(A_log[d * NS_]);
    float eps[16];
#pragma unroll
    for (int n = 0; n < 16; n++)
        eps[n] = -__expf(A_log[d * NS_ + n]) - (float)(n + 1) * negA0;
    float dp = Dp[d];

    size_t xbase = ((size_t)b * L_ + (size_t)w * CHL) * D_ + d;
    size_t ebase = ((size_t)b * L_ + (size_t)w * CHL) * E_ + R_ + lane;

    float st[16], pa[16];
#pragma unroll
    for (int n = 0; n < 16; n++) { st[n] = 0.0f; pa[n] = 1.0f; }

    // Phase A
    {
        float pdl[4], pxv[4];
#pragma unroll
        for (int i = 0; i < 4; i++) {
            pdl[i] = delta[xbase + (size_t)i * D_];
            pxv[i] = h0[xbase + (size_t)i * D_];
        }
#pragma unroll
        for (int sub = 0; sub < CHL / SUBL; sub++) {
            float* bcw = sBC + (w * SUBL) * 32;
#pragma unroll 8
            for (int l = 0; l < SUBL; l++)
                bcw[l * 32 + lane] =
                    dbc[ebase + (size_t)(sub * SUBL + l) * E_];
            __syncwarp();

#pragma unroll 4
            for (int l = 0; l < SUBL; l++) {
                int gl = sub * SUBL + l;
                float dv = pdl[gl & 3];
                float xv = pxv[gl & 3];
                int lf = gl + 4;
                if (lf < CHL) {
                    pdl[gl & 3] = delta[xbase + (size_t)lf * D_];
                    pxv[gl & 3] = h0[xbase + (size_t)lf * D_];
                }

                float Bv[16];
                *(float4*)&Bv[0]  = *(const float4*)&bcw[l * 32 + 0];
                *(float4*)&Bv[4]  = *(const float4*)&bcw[l * 32 + 4];
                *(float4*)&Bv[8]  = *(const float4*)&bcw[l * 32 + 8];
                *(float4*)&Bv[12] = *(const float4*)&bcw[l * 32 + 12];

                float p = __expf(dv * negA0);
                float p2 = p * p, p4 = p2 * p2, p8 = p4 * p4;
                float pw[16];
                pw[0] = p;          pw[1] = p2;         pw[2] = p2 * p;
                pw[3] = p4;         pw[4] = p4 * p;     pw[5] = p4 * p2;
                pw[6] = p4 * pw[2]; pw[7] = p8;
                pw[8] = p8 * p;     pw[9] = p8 * p2;    pw[10] = p8 * pw[2];
                pw[11] = p8 * p4;   pw[12] = p8 * pw[4]; pw[13] = p8 * pw[5];
                pw[14] = p8 * pw[6]; pw[15] = p8 * p8;

                float dx = dv * xv;
#pragma unroll
                for (int n = 0; n < 16; n++) {
                    float a = pw[n] * fmaf(dv, eps[n], 1.0f);
                    st[n] = fmaf(a, st[n], dx * Bv[n]);
                    pa[n] *= a;
                }
            }
            __syncwarp();
        }
    }

#pragma unroll
    for (int n = 0; n < 16; n++) {
        sPA[(w * NS_ + n) * 32 + lane] = pa[n];
        sST[(w * NS_ + n) * 32 + lane] = st[n];
    }
    __syncthreads();

    // Phase B
    {
        int cd = tid & 31;
        int cn = tid >> 5;
        float hacc = 0.0f;
#pragma unroll
        for (int wc = 0; wc < NCH; wc++) {
            int off = (wc * NS_ + cn) * 32 + cd;
            float pav = sPA[off];
            float stv = sST[off];
            sPA[off] = hacc;
            hacc = fmaf(pav, hacc, stv);
        }
    }
    __syncthreads();

    // Phase C
#pragma unroll
    for (int n = 0; n < 16; n++) st[n] = sPA[(w * NS_ + n) * 32 + lane];

    {
        float pdl[4], pxv[4];
#pragma unroll
        for (int i = 0; i < 4; i++) {
            pdl[i] = delta[xbase + (size_t)i * D_];
            pxv[i] = h0[xbase + (size_t)i * D_];
        }
#pragma unroll
        for (int sub = 0; sub < CHL / SUBL; sub++) {
            float* bcw = sBC + (w * SUBL) * 32;
#pragma unroll 8
            for (int l = 0; l < SUBL; l++)
                bcw[l * 32 + lane] =
                    dbc[ebase + (size_t)(sub * SUBL + l) * E_];
            __syncwarp();

#pragma unroll 4
            for (int l = 0; l < SUBL; l++) {
                int gl = sub * SUBL + l;
                float dv = pdl[gl & 3];
                float xv = pxv[gl & 3];
                int lf = gl + 4;
                if (lf < CHL) {
                    pdl[gl & 3] = delta[xbase + (size_t)lf * D_];
                    pxv[gl & 3] = h0[xbase + (size_t)lf * D_];
                }

                float Bv[16], Cv[16];
                *(float4*)&Bv[0]  = *(const float4*)&bcw[l * 32 + 0];
                *(float4*)&Bv[4]  = *(const float4*)&bcw[l * 32 + 4];
                *(float4*)&Bv[8]  = *(const float4*)&bcw[l * 32 + 8];
                *(float4*)&Bv[12] = *(const float4*)&bcw[l * 32 + 12];
                *(float4*)&Cv[0]  = *(const float4*)&bcw[l * 32 + 16];
                *(float4*)&Cv[4]  = *(const float4*)&bcw[l * 32 + 20];
                *(float4*)&Cv[8]  = *(const float4*)&bcw[l * 32 + 24];
                *(float4*)&Cv[12] = *(const float4*)&bcw[l * 32 + 28];

                float p = __expf(dv * negA0);
                float p2 = p * p, p4 = p2 * p2, p8 = p4 * p4;
                float pw[16];
                pw[0] = p;          pw[1] = p2;         pw[2] = p2 * p;
                pw[3] = p4;         pw[4] = p4 * p;     pw[5] = p4 * p2;
                pw[6] = p4 * pw[2]; pw[7] = p8;
                pw[8] = p8 * p;     pw[9] = p8 * p2;    pw[10] = p8 * pw[2];
                pw[11] = p8 * p4;   pw[12] = p8 * pw[4]; pw[13] = p8 * pw[5];
                pw[14] = p8 * pw[6]; pw[15] = p8 * p8;

                float dx = dv * xv;
                float y0 = 0.f, y1 = 0.f, y2 = 0.f, y3 = 0.f;
#pragma unroll
                for (int n = 0; n < 16; n++) {
                    float a = pw[n] * fmaf(dv, eps[n], 1.0f);
                    st[n] = fmaf(a, st[n], dx * Bv[n]);
                    float yv = st[n] * Cv[n];
                    if ((n & 3) == 0) y0 += yv;
                    else if ((n & 3) == 1) y1 += yv;
                    else if ((n & 3) == 2) y2 += yv;
                    else y3 += yv;
                }
                float y = (y0 + y1) + (y2 + y3);
                hout[xbase + (size_t)gl * D_] = fmaf(xv, dp, xv + y);
            }
            __syncwarp();
        }
    }
}

// ---------------------------------------------------------------------------
// Launch
// ---------------------------------------------------------------------------
extern "C" void kernel_launch(void* const* d_in, const int* in_sizes, int n_in,
                              void* d_out, int out_size) {
    const float* x      = (const float*)d_in[0];
    const float* ln1_w  = (const float*)d_in[1];
    const float* ln2_w  = (const float*)d_in[2];
    const float* W_dbc  = (const float*)d_in[3];
    const float* W_dt   = (const float*)d_in[4];
    const float* b_dt   = (const float*)d_in[5];
    const float* A_log  = (const float*)d_in[6];
    const float* Dp     = (const float*)d_in[7];
    const float* W_fc   = (const float*)d_in[8];
    const float* W_proj = (const float*)d_in[9];
    float* out = (float*)d_out;

    float *h0, *dbc, *delta, *h;
    __nv_bfloat16 *h0h, *h0l, *wdbh, *wdbl;
    __half *m0f, *fcf, *wfcf, *wprf;
    cudaGetSymbolAddress((void**)&h0, g_h0);
    cudaGetSymbolAddress((void**)&dbc, g_dbc);
    cudaGetSymbolAddress((void**)&delta, g_delta);
    cudaGetSymbolAddress((void**)&h, g_h);
    cudaGetSymbolAddress((void**)&h0h, g_h0h);
    cudaGetSymbolAddress((void**)&h0l, g_h0l);
    cudaGetSymbolAddress((void**)&wdbh, g_wdbh);
    cudaGetSymbolAddress((void**)&wdbl, g_wdbl);
    cudaGetSymbolAddress((void**)&m0f, g_m0f);
    cudaGetSymbolAddress((void**)&fcf, g_fcf);
    cudaGetSymbolAddress((void**)&wfcf, g_wfcf);
    cudaGetSymbolAddress((void**)&wprf, g_wprf);

    cudaFuncSetAttribute(gemm_hmma_kernel<1>,
                         cudaFuncAttributeMaxDynamicSharedMemorySize,
                         HSMEM_TOTAL);
    cudaFuncSetAttribute(gemm_hmma_kernel<2>,
                         cudaFuncAttributeMaxDynamicSharedMemorySize,
                         HSMEM_TOTAL);
    cudaFuncSetAttribute(gemm_wmma_dbc_kernel,
                         cudaFuncAttributeMaxDynamicSharedMemorySize,
                         SSMEM_TOTAL);
    cudaFuncSetAttribute(scan3_kernel,
                         cudaFuncAttributeMaxDynamicSharedMemorySize,
                         SC3_SMEM);

    // 1. h0 = softplus(ln1(x)) (+ fused W_dbc bf16 split)
    ln1_fused_kernel<<<ML_ + E_ * D_ / 1024, 256>>>(x, ln1_w, W_dbc, h0, h0h,
                                                    h0l, wdbh, wdbl);

    // 2. dbc = h0 @ W_dbc^T   (M=4096, N=96, K=1024) [bf16 3-term WMMA]
    gemm_wmma_dbc_kernel<<<ML_ / 64, 128, SSMEM_TOTAL>>>(h0h, h0l, wdbh, wdbl,
                                                         dbc);

    // 3. delta = softplus(dbc[:, :64] @ W_dt^T + b_dt)
    gemm_kernel<1, true><<<dim3(D_ / TBN, ML_ / TBM), 256>>>(
        dbc, E_, W_dt, R_, b_dt, delta, D_, ML_, D_, R_);

    // 4. h = h0 + ssm(h0)   [chunked block-parallel scan]
    scan3_kernel<<<dim3(D_ / 32, B_), 512, SC3_SMEM>>>(h0, delta, dbc, A_log,
                                                       Dp, h);

    // 5-6. Weight converts for the big GEMMs (fp16 single)
    hconv_kernel<<<F_ * D_ / 1024, 256>>>(W_fc, wfcf, F_ * D_ / 4);
    hconv_kernel<<<D_ * F_ / 1024, 256>>>(W_proj, wprf, D_ * F_ / 4);

    // 7. m0 = ln2(h) -> fp16
    ln2_kernel<<<ML_, 256>>>(h, ln2_w, m0f);

    // 8. fc = gelu(m0 @ W_fc^T) -> fp16   (M=4096, N=4096, K=1024)
    gemm_hmma_kernel<1><<<dim3(F_ / 128, ML_ / 256), 256, HSMEM_TOTAL>>>(
        m0f, wfcf, D_, fcf, nullptr, nullptr, F_);

    // 9. out = h + fc @ W_proj^T   (M=4096, N=1024, K=4096)
    gemm_hmma_kernel<2><<<dim3(D_ / 128, ML_ / 256), 256, HSMEM_TOTAL>>>(
        fcf, wprf, F_, nullptr, out, h, D_);
}

// round 14
// speedup vs baseline: 1.0661x; 1.0661x over previous
#include <cuda_runtime.h>
#include <cuda_bf16.h>
#include <cuda_fp16.h>
#include <mma.h>
#include <math.h>
#include <stdint.h>

using namespace nvcuda;

// Shapes (fixed by the problem)
#define B_ 4
#define L_ 1024
#define D_ 1024
#define NS_ 16
#define R_ 64
#define E_ 96          // R + 2N
#define F_ 4096        // 4*D
#define ML_ (B_ * L_)  // 4096

// ---------------------------------------------------------------------------
// Scratch (no allocations allowed -> __device__ globals)
// ---------------------------------------------------------------------------
__device__ float g_h0[(size_t)ML_ * D_];     // softplus(ln1(x))
__device__ float g_dbc[(size_t)ML_ * E_];    // h0 @ W_dbc^T
__device__ float g_dbcp[4][(size_t)ML_ * E_];  // split-K partials
__device__ float g_delta[(size_t)ML_ * D_];  // softplus(dlr @ W_dt^T + b_dt)
__device__ float g_h[(size_t)ML_ * D_];      // h0 + ssm(h0)

// bf16 hi/lo split (dbc path only — precision-sensitive)
__device__ __nv_bfloat16 g_h0h[(size_t)ML_ * D_];
__device__ __nv_bfloat16 g_h0l[(size_t)ML_ * D_];
__device__ __nv_bfloat16 g_wdbh[(size_t)E_ * D_];
__device__ __nv_bfloat16 g_wdbl[(size_t)E_ * D_];

// fp16 single operands for the two big GEMMs
__device__ __half g_m0f[(size_t)ML_ * D_];
__device__ __half g_fcf[(size_t)ML_ * F_];
__device__ __half g_wfcf[(size_t)F_ * D_];
__device__ __half g_wprf[(size_t)D_ * F_];

// ---------------------------------------------------------------------------
// Activations
// ---------------------------------------------------------------------------
__device__ __forceinline__ float softplus_f(float v) {
    return fmaxf(v, 0.0f) + log1pf(__expf(-fabsf(v)));
}
__device__ __forceinline__ float gelu_f(float v) {
    const float c = 0.7978845608028654f;
    float v3 = v * v * v;
    return 0.5f * v * (1.0f + tanhf(c * (v + 0.044715f * v3)));
}

// ---------------------------------------------------------------------------
// PTX helpers
// ---------------------------------------------------------------------------
__device__ __forceinline__ uint32_t smem_u32(const void* p) {
    uint32_t a;
    asm("{ .reg .u64 t; cvta.to.shared.u64 t, %1; cvt.u32.u64 %0, t; }"
        : "=r"(a) : "l"(p));
    return a;
}
__device__ __forceinline__ void cp_async8(uint32_t dst, const void* src) {
    asm volatile("cp.async.ca.shared.global [%0], [%1], 8;\n"
                 :: "r"(dst), "l"(src));
}
__device__ __forceinline__ void cp_commit() {
    asm volatile("cp.async.commit_group;\n" ::: "memory");
}
template <int N>
__device__ __forceinline__ void cp_wait() {
    asm volatile("cp.async.wait_group %0;\n" :: "n"(N) : "memory");
}

// ---------------------------------------------------------------------------
// Big HMMA fp16 GEMM (R9 config): CTA 128x128, BK=64, 8 warps (4x2),
// warp tile 32x64, double-buffered cp.async.
// EPI==1: C = gelu(acc) -> fp16 Ch.   EPI==2: C = acc + addv -> fp32 Cf.
// ---------------------------------------------------------------------------
#define HPAD 72                      // halves per row (64 + 8); 144B stride
#define HTILE_B (128 * HPAD * 2)     // 18432 bytes
#define HSTG_B (2 * HTILE_B)         // 36864 bytes per stage (A + B)
#define HSMEM_TOTAL (2 * HSTG_B)     // 73728 bytes (>= 64KB epilogue staging)

template <int EPI>
__global__ __launch_bounds__(256) void gemm_hmma_kernel(
    const __half* __restrict__ A, const __half* __restrict__ Bm, int K,
    __half* __restrict__ Ch, float* __restrict__ Cf,
    const float* __restrict__ addv, int ldc) {
    extern __shared__ char dsm[];
    int tid = threadIdx.x;
    int wid = tid >> 5;
    int wm = wid >> 1;
    int wn = wid & 1;
    int bm = blockIdx.y * 128;
    int bn = blockIdx.x * 128;

    wmma::fragment<wmma::accumulator, 16, 16, 16, float> acc[2][4];
#pragma unroll
    for (int i = 0; i < 2; i++)
#pragma unroll
        for (int j = 0; j < 4; j++) wmma::fill_fragment(acc[i][j], 0.0f);

    auto load_chunk = [&](int st, int kc) {
        uint32_t sb = smem_u32(dsm) + st * HSTG_B;
        int k0 = kc * 64;
#pragma unroll
        for (int j = 0; j < 8; j++) {
            int idx = tid + j * 256;   // 0..2047
            int r = idx >> 4;          // 0..127
            int g = idx & 15;          // 16 groups of 4 halves
            uint32_t so = (uint32_t)(r * (HPAD * 2) + g * 8);
            cp_async8(sb + so, A + (size_t)(bm + r) * K + k0 + g * 4);
            cp_async8(sb + HTILE_B + so,
                      Bm + (size_t)(bn + r) * K + k0 + g * 4);
        }
    };

    const int NC = K / 64;
    load_chunk(0, 0);
    cp_commit();

    for (int kc = 0; kc < NC; kc++) {
        int st = kc & 1;
        if (kc + 1 < NC) {
            load_chunk(st ^ 1, kc + 1);
            cp_commit();
            cp_wait<1>();
        } else {
            cp_wait<0>();
        }
        __syncthreads();

        const __half* sA = (const __half*)(dsm + st * HSTG_B);
        const __half* sB = (const __half*)(dsm + st * HSTG_B + HTILE_B);

#pragma unroll
        for (int kk = 0; kk < 64; kk += 16) {
            wmma::fragment<wmma::matrix_a, 16, 16, 16, __half,
                           wmma::row_major> fa[2];
            wmma::fragment<wmma::matrix_b, 16, 16, 16, __half,
                           wmma::col_major> fb[4];
#pragma unroll
            for (int i = 0; i < 2; i++)
                wmma::load_matrix_sync(fa[i],
                                       sA + (wm * 32 + i * 16) * HPAD + kk,
                                       HPAD);
#pragma unroll
            for (int j = 0; j < 4; j++)
                wmma::load_matrix_sync(fb[j],
                                       sB + (wn * 64 + j * 16) * HPAD + kk,
                                       HPAD);
#pragma unroll
            for (int i = 0; i < 2; i++)
#pragma unroll
                for (int j = 0; j < 4; j++)
                    wmma::mma_sync(acc[i][j], fa[i], fb[j], acc[i][j]);
        }
        __syncthreads();
    }

    // Epilogue via smem fp32 staging tile for coalesced writes
    float* sC = (float*)dsm;
#pragma unroll
    for (int i = 0; i < 2; i++)
#pragma unroll
        for (int j = 0; j < 4; j++)
            wmma::store_matrix_sync(sC + (wm * 32 + i * 16) * 128 +
                                        (wn * 64 + j * 16),
                                    acc[i][j], 128, wmma::mem_row_major);
    __syncthreads();

#pragma unroll
    for (int it = 0; it < 16; it++) {
        int idx = tid + it * 256;
        int r = idx >> 5;
        int c4 = idx & 31;
        float4 v = ((const float4*)(sC + r * 128))[c4];
        size_t row = bm + r;
        size_t col = bn + c4 * 4;
        if (EPI == 1) {
            __half o[4];
            o[0] = __float2half(gelu_f(v.x));
            o[1] = __float2half(gelu_f(v.y));
            o[2] = __float2half(gelu_f(v.z));
            o[3] = __float2half(gelu_f(v.w));
            *(uint2*)(Ch + row * ldc + col) = *(uint2*)o;
        } else {
            const float4 av = *(const float4*)(addv + row * ldc + col);
            *(float4*)(Cf + row * ldc + col) =
                make_float4(v.x + av.x, v.y + av.y, v.z + av.z, v.w + av.w);
        }
    }
}

// ---------------------------------------------------------------------------
// dbc split-K v2: C_partial[kz][4096,96] = Ah/Al[:,kz*256:+256] @ B^T slice.
// Grid (32, 4): 32 M-blocks of 128 rows x 4 K-splits. 256 threads, 8 warps.
// bf16 3-term compensation (precision-sensitive path).
// ---------------------------------------------------------------------------
#define S2PAD 36
#define S2A (128 * S2PAD * 2)        // 9216 B per A tile
#define S2B (96 * S2PAD * 2)         // 6912 B per B tile
#define S2STG (2 * S2A + 2 * S2B)    // 32256 B per stage
#define S2TOT (2 * S2STG)            // 64512 B

__global__ __launch_bounds__(256) void gemm_dbc2_kernel(
    const __nv_bfloat16* __restrict__ Ah, const __nv_bfloat16* __restrict__ Al,
    const __nv_bfloat16* __restrict__ Bh, const __nv_bfloat16* __restrict__ Bl,
    float* __restrict__ P) {
    extern __shared__ char dsm[];
    int tid = threadIdx.x;
    int wid = tid >> 5;
    int bm = blockIdx.x * 128;
    int kz = blockIdx.y;
    const int K = D_;
    const int k0base = kz * 256;
    float* C = P + (size_t)kz * ML_ * E_;

    wmma::fragment<wmma::accumulator, 16, 16, 16, float> acc[6];
#pragma unroll
    for (int j = 0; j < 6; j++) wmma::fill_fragment(acc[j], 0.0f);

    auto load_chunk = [&](int st, int kc) {
        uint32_t sb = smem_u32(dsm) + st * S2STG;
        int k0 = k0base + kc * 32;
#pragma unroll
        for (int j = 0; j < 4; j++) {  // A: 128 rows x 8 groups = 1024 slots
            int idx = tid + j * 256;
            int r = idx >> 3, cg = idx & 7;
            uint32_t so = (uint32_t)(r * (S2PAD * 2) + cg * 8);
            size_t ao = (size_t)(bm + r) * K + k0 + cg * 4;
            cp_async8(sb + so, Ah + ao);
            cp_async8(sb + S2A + so, Al + ao);
        }
#pragma unroll
        for (int j = 0; j < 3; j++) {  // B: 96 rows x 8 groups = 768 slots
            int idx = tid + j * 256;
            int r = idx >> 3, cg = idx & 7;
            uint32_t so = (uint32_t)(r * (S2PAD * 2) + cg * 8);
            size_t bo = (size_t)r * K + k0 + cg * 4;
            cp_async8(sb + 2 * S2A + so, Bh + bo);
            cp_async8(sb + 2 * S2A + S2B + so, Bl + bo);
        }
    };

    const int NC = 8;  // 256 / 32
    load_chunk(0, 0);
    cp_commit();

    for (int kc = 0; kc < NC; kc++) {
        int st = kc & 1;
        if (kc + 1 < NC) {
            load_chunk(st ^ 1, kc + 1);
            cp_commit();
            cp_wait<1>();
        } else {
            cp_wait<0>();
        }
        __syncthreads();

        const __nv_bfloat16* sAh = (const __nv_bfloat16*)(dsm + st * S2STG);
        const __nv_bfloat16* sAl =
            (const __nv_bfloat16*)(dsm + st * S2STG + S2A);
        const __nv_bfloat16* sBh =
            (const __nv_bfloat16*)(dsm + st * S2STG + 2 * S2A);
        const __nv_bfloat16* sBl =
            (const __nv_bfloat16*)(dsm + st * S2STG + 2 * S2A + S2B);

#pragma unroll
        for (int kk = 0; kk < 32; kk += 16) {
            wmma::fragment<wmma::matrix_a, 16, 16, 16, __nv_bfloat16,
                           wmma::row_major> fah, fal;
            wmma::fragment<wmma::matrix_b, 16, 16, 16, __nv_bfloat16,
                           wmma::col_major> fbh[6], fbl[6];
            int r0 = wid * 16;
            wmma::load_matrix_sync(fah, sAh + r0 * S2PAD + kk, S2PAD);
            wmma::load_matrix_sync(fal, sAl + r0 * S2PAD + kk, S2PAD);
#pragma unroll
            for (int j = 0; j < 6; j++) {
                wmma::load_matrix_sync(fbh[j], sBh + j * 16 * S2PAD + kk,
                                       S2PAD);
                wmma::load_matrix_sync(fbl[j], sBl + j * 16 * S2PAD + kk,
                                       S2PAD);
            }
#pragma unroll
            for (int j = 0; j < 6; j++) {
                wmma::mma_sync(acc[j], fah, fbh[j], acc[j]);
                wmma::mma_sync(acc[j], fal, fbh[j], acc[j]);
                wmma::mma_sync(acc[j], fah, fbl[j], acc[j]);
            }
        }
        __syncthreads();
    }

    float* sC = (float*)dsm;  // 128 x 96 f32 = 49152 B
#pragma unroll
    for (int j = 0; j < 6; j++)
        wmma::store_matrix_sync(sC + (wid * 16) * 96 + j * 16, acc[j], 96,
                                wmma::mem_row_major);
    __syncthreads();

#pragma unroll
    for (int it = 0; it < 12; it++) {
        int idx = tid + it * 256;  // 3072 float4 slots
        int r = idx / 24;
        int c4 = idx % 24;
        float4 v = ((const float4*)sC)[idx];
        *(float4*)(C + (size_t)(bm + r) * E_ + c4 * 4) = v;
    }
}

// Deterministic fixed-order reduce of 4 split-K partials.
__global__ __launch_bounds__(256) void dbcred_kernel(const float* __restrict__ P,
                                                     float* __restrict__ C) {
    int i = blockIdx.x * 256 + threadIdx.x;  // float4 index < 98304
    const size_t stride = (size_t)ML_ * E_ / 4;
    const float4* p = (const float4*)P;
    float4 a = p[i];
    float4 b = p[stride + i];
    float4 c = p[2 * stride + i];
    float4 d = p[3 * stride + i];
    float4 o = make_float4(((a.x + b.x) + (c.x + d.x)),
                           ((a.y + b.y) + (c.y + d.y)),
                           ((a.z + b.z) + (c.z + d.z)),
                           ((a.w + b.w) + (c.w + d.w)));
    ((float4*)C)[i] = o;
}

// ---------------------------------------------------------------------------
// ln1 mega-fused. Block ranges:
//  [0, ML_)              : softplus(ln(x)) -> fp32 + bf16 hi/lo
//  [ML_, ML_+96)         : W_dbc fp32 -> bf16 hi/lo split
//  [ML_+96, +4096)       : W_fc fp32 -> fp16
//  [ML_+4192, +4096)     : W_proj fp32 -> fp16
// ---------------------------------------------------------------------------
#define LN1_GRID (ML_ + 96 + 4096 + 4096)

__global__ __launch_bounds__(256) void ln1_mega_kernel(
    const float* __restrict__ x, const float* __restrict__ w,
    const float* __restrict__ W_dbc, const float* __restrict__ W_fc,
    const float* __restrict__ W_proj,
    float* __restrict__ out, __nv_bfloat16* __restrict__ oh,
    __nv_bfloat16* __restrict__ ol,
    __nv_bfloat16* __restrict__ wdh, __nv_bfloat16* __restrict__ wdl,
    __half* __restrict__ wfcf, __half* __restrict__ wprf) {
    __shared__ float red[8];
    int bid = blockIdx.x;
    int t = threadIdx.x;

    if (bid >= ML_) {
        int r = bid - ML_;
        if (r < 96) {  // W_dbc bf16 hi/lo split
            int i = r * 256 + t;
            float4 v = ((const float4*)W_dbc)[i];
            float vv[4] = {v.x, v.y, v.z, v.w};
            __nv_bfloat16 h[4], l[4];
#pragma unroll
            for (int j = 0; j < 4; j++) {
                h[j] = __float2bfloat16(vv[j]);
                l[j] = __float2bfloat16(vv[j] - __bfloat162float(h[j]));
            }
            ((uint2*)wdh)[i] = *(uint2*)h;
            ((uint2*)wdl)[i] = *(uint2*)l;
        } else if (r < 96 + 4096) {  // W_fc -> fp16
            int i = (r - 96) * 256 + t;
            float4 v = ((const float4*)W_fc)[i];
            __half h[4] = {__float2half(v.x), __float2half(v.y),
                           __float2half(v.z), __float2half(v.w)};
            ((uint2*)wfcf)[i] = *(uint2*)h;
        } else {  // W_proj -> fp16
            int i = (r - 96 - 4096) * 256 + t;
            float4 v = ((const float4*)W_proj)[i];
            __half h[4] = {__float2half(v.x), __float2half(v.y),
                           __float2half(v.z), __float2half(v.w)};
            ((uint2*)wprf)[i] = *(uint2*)h;
        }
        return;
    }

    int row = bid;
    const float4* xr = (const float4*)(x + (size_t)row * D_);
    float4 v = xr[t];

    float s = v.x + v.y + v.z + v.w;
#pragma unroll
    for (int m = 16; m > 0; m >>= 1) s += __shfl_xor_sync(0xffffffffu, s, m);
    if ((t & 31) == 0) red[t >> 5] = s;
    __syncthreads();
    float tot = 0.0f;
#pragma unroll
    for (int i = 0; i < 8; i++) tot += red[i];
    float mu = tot * (1.0f / D_);

    float cx = v.x - mu, cy = v.y - mu, cz = v.z - mu, cw = v.w - mu;
    float s2 = cx * cx + cy * cy + cz * cz + cw * cw;
#pragma unroll
    for (int m = 16; m > 0; m >>= 1) s2 += __shfl_xor_sync(0xffffffffu, s2, m);
    __syncthreads();
    if ((t & 31) == 0) red[t >> 5] = s2;
    __syncthreads();
    float tot2 = 0.0f;
#pragma unroll
    for (int i = 0; i < 8; i++) tot2 += red[i];
    float rs = rsqrtf(tot2 * (1.0f / D_) + 1e-5f);

    float4 wv = ((const float4*)w)[t];
    float o[4];
    o[0] = softplus_f(cx * rs * wv.x);
    o[1] = softplus_f(cy * rs * wv.y);
    o[2] = softplus_f(cz * rs * wv.z);
    o[3] = softplus_f(cw * rs * wv.w);
    ((float4*)(out + (size_t)row * D_))[t] = make_float4(o[0], o[1], o[2], o[3]);

    __nv_bfloat16 h[4], l[4];
#pragma unroll
    for (int j = 0; j < 4; j++) {
        h[j] = __float2bfloat16(o[j]);
        l[j] = __float2bfloat16(o[j] - __bfloat162float(h[j]));
    }
    ((uint2*)(oh + (size_t)row * D_))[t] = *(uint2*)h;
    ((uint2*)(ol + (size_t)row * D_))[t] = *(uint2*)l;
}

// ---------------------------------------------------------------------------
// ln2: ln(h) -> fp16 single
// ---------------------------------------------------------------------------
__global__ __launch_bounds__(256) void ln2_kernel(const float* __restrict__ x,
                                                  const float* __restrict__ w,
                                                  __half* __restrict__ o16) {
    int row = blockIdx.x;
    int t = threadIdx.x;
    __shared__ float red[8];

    const float4* xr = (const float4*)(x + (size_t)row * D_);
    float4 v = xr[t];

    float s = v.x + v.y + v.z + v.w;
#pragma unroll
    for (int m = 16; m > 0; m >>= 1) s += __shfl_xor_sync(0xffffffffu, s, m);
    if ((t & 31) == 0) red[t >> 5] = s;
    __syncthreads();
    float tot = 0.0f;
#pragma unroll
    for (int i = 0; i < 8; i++) tot += red[i];
    float mu = tot * (1.0f / D_);

    float cx = v.x - mu, cy = v.y - mu, cz = v.z - mu, cw = v.w - mu;
    float s2 = cx * cx + cy * cy + cz * cz + cw * cw;
#pragma unroll
    for (int m = 16; m > 0; m >>= 1) s2 += __shfl_xor_sync(0xffffffffu, s2, m);
    __syncthreads();
    if ((t & 31) == 0) red[t >> 5] = s2;
    __syncthreads();
    float tot2 = 0.0f;
#pragma unroll
    for (int i = 0; i < 8; i++) tot2 += red[i];
    float rs = rsqrtf(tot2 * (1.0f / D_) + 1e-5f);

    float4 wv = ((const float4*)w)[t];
    __half h[4];
    h[0] = __float2half(cx * rs * wv.x);
    h[1] = __float2half(cy * rs * wv.y);
    h[2] = __float2half(cz * rs * wv.z);
    h[3] = __float2half(cw * rs * wv.w);
    ((uint2*)(o16 + (size_t)row * D_))[t] = *(uint2*)h;
}

// ---------------------------------------------------------------------------
// SIMT fp32 GEMM (delta GEMM): C = softplus(A @ B^T + bias)
// ---------------------------------------------------------------------------
#define TBM 128
#define TBN 128
#define TBK 8

template <int ACT, bool HAS_BIAS>
__global__ __launch_bounds__(256) void gemm_kernel(
    const float* __restrict__ A, int lda,
    const float* __restrict__ Bm, int ldb,
    const float* __restrict__ bias,
    float* __restrict__ C, int ldc,
    int M, int N, int K) {
    __shared__ float As[TBK][TBM];
    __shared__ float Bs[TBK][TBN];

    int tid = threadIdx.x;
    int bm = blockIdx.y * TBM;
    int bn = blockIdx.x * TBN;
    int tx = tid & 15;
    int ty = tid >> 4;

    float acc[8][8];
#pragma unroll
    for (int i = 0; i < 8; i++)
#pragma unroll
        for (int j = 0; j < 8; j++) acc[i][j] = 0.0f;

    int trow = tid >> 1;
    int tq = (tid & 1) * 4;
    const float* Aptr = A + (size_t)(bm + trow) * lda + tq;
    bool bvalid = (bn + trow) < N;
    const float* Bptr = Bm + (size_t)(bn + trow) * ldb + tq;

    for (int k0 = 0; k0 < K; k0 += TBK) {
        float4 av = *(const float4*)(Aptr + k0);
        float4 bv = bvalid ? *(const float4*)(Bptr + k0)
                           : make_float4(0.f, 0.f, 0.f, 0.f);
        As[tq + 0][trow] = av.x; As[tq + 1][trow] = av.y;
        As[tq + 2][trow] = av.z; As[tq + 3][trow] = av.w;
        Bs[tq + 0][trow] = bv.x; Bs[tq + 1][trow] = bv.y;
        Bs[tq + 2][trow] = bv.z; Bs[tq + 3][trow] = bv.w;
        __syncthreads();
#pragma unroll
        for (int kk = 0; kk < TBK; kk++) {
            float ra[8], rb[8];
            *(float4*)&ra[0] = *(const float4*)&As[kk][ty * 4];
            *(float4*)&ra[4] = *(const float4*)&As[kk][64 + ty * 4];
            *(float4*)&rb[0] = *(const float4*)&Bs[kk][tx * 4];
            *(float4*)&rb[4] = *(const float4*)&Bs[kk][64 + tx * 4];
#pragma unroll
            for (int i = 0; i < 8; i++)
#pragma unroll
                for (int j = 0; j < 8; j++)
                    acc[i][j] = fmaf(ra[i], rb[j], acc[i][j]);
        }
        __syncthreads();
    }

    int rows[8], cols[8];
#pragma unroll
    for (int i = 0; i < 4; i++) {
        rows[i] = bm + ty * 4 + i;
        rows[i + 4] = bm + 64 + ty * 4 + i;
        cols[i] = bn + tx * 4 + i;
        cols[i + 4] = bn + 64 + tx * 4 + i;
    }
#pragma unroll
    for (int i = 0; i < 8; i++) {
#pragma unroll
        for (int j = 0; j < 8; j++) {
            int gc = cols[j];
            if (gc >= N) continue;
            float v = acc[i][j];
            if (HAS_BIAS) v += bias[gc];
            if (ACT == 1) v = softplus_f(v);
            C[(size_t)rows[i] * ldc + gc] = v;
        }
    }
}

// ---------------------------------------------------------------------------
// Selective scan v3.1: block-local chunked parallel scan.
// Phase A now tracks sum-of-deltas; chunk combine factor = exp(negA_n * sum)
// exactly (Π exp(δ_t A_n) = exp(A_n Σδ_t)), removing 16 muls/step.
// ---------------------------------------------------------------------------
#define NCH 16
#define CHL 64
#define SUBL 32

#define SC3_BC 0
#define SC3_PA 65536
#define SC3_ST 98304
#define SC3_SMEM 131072

__global__ __launch_bounds__(512) void scan3_kernel(
    const float* __restrict__ h0, const float* __restrict__ delta,
    const float* __restrict__ dbc, const float* __restrict__ A_log,
    const float* __restrict__ Dp, float* __restrict__ hout) {
    extern __shared__ char dsm[];
    float* sBC = (float*)(dsm + SC3_BC);
    float* sPA = (float*)(dsm + SC3_PA);
    float* sST = (float*)(dsm + SC3_ST);

    int tid = threadIdx.x;
    int lane = tid & 31;
    int w = tid >> 5;
    int d = blockIdx.x * 32 + lane;
    int b = blockIdx.y;

    float negA0 = -__expf(A_log[d * NS_]);
    float eps[16];
#pragma unroll
    for (int n = 0; n < 16; n++)
        eps[n] = -__expf(A_log[d * NS_ + n]) - (float)(n + 1) * negA0;
    float dp = Dp[d];

    size_t xbase = ((size_t)b * L_ + (size_t)w * CHL) * D_ + d;
    size_t ebase = ((size_t)b * L_ + (size_t)w * CHL) * E_ + R_ + lane;

    float st[16];
#pragma unroll
    for (int n = 0; n < 16; n++) st[n] = 0.0f;
    float sdelta = 0.0f;

    // Phase A: local scan from zero state + sum of deltas
    {
        float pdl[4], pxv[4];
#pragma unroll
        for (int i = 0; i < 4; i++) {
            pdl[i] = delta[xbase + (size_t)i * D_];
            pxv[i] = h0[xbase + (size_t)i * D_];
        }
#pragma unroll
        for (int sub = 0; sub < CHL / SUBL; sub++) {
            float* bcw = sBC + (w * SUBL) * 32;
#pragma unroll 8
            for (int l = 0; l < SUBL; l++)
                bcw[l * 32 + lane] =
                    dbc[ebase + (size_t)(sub * SUBL + l) * E_];
            __syncwarp();

#pragma unroll 4
            for (int l = 0; l < SUBL; l++) {
                int gl = sub * SUBL + l;
                float dv = pdl[gl & 3];
                float xv = pxv[gl & 3];
                int lf = gl + 4;
                if (lf < CHL) {
                    pdl[gl & 3] = delta[xbase + (size_t)lf * D_];
                    pxv[gl & 3] = h0[xbase + (size_t)lf * D_];
                }

                float Bv[16];
                *(float4*)&Bv[0]  = *(const float4*)&bcw[l * 32 + 0];
                *(float4*)&Bv[4]  = *(const float4*)&bcw[l * 32 + 4];
                *(float4*)&Bv[8]  = *(const float4*)&bcw[l * 32 + 8];
                *(float4*)&Bv[12] = *(const float4*)&bcw[l * 32 + 12];

                float p = __expf(dv * negA0);
                float p2 = p * p, p4 = p2 * p2, p8 = p4 * p4;
                float pw[16];
                pw[0] = p;          pw[1] = p2;         pw[2] = p2 * p;
                pw[3] = p4;         pw[4] = p4 * p;     pw[5] = p4 * p2;
                pw[6] = p4 * pw[2]; pw[7] = p8;
                pw[8] = p8 * p;     pw[9] = p8 * p2;    pw[10] = p8 * pw[2];
                pw[11] = p8 * p4;   pw[12] = p8 * pw[4]; pw[13] = p8 * pw[5];
                pw[14] = p8 * pw[6]; pw[15] = p8 * p8;

                sdelta += dv;
                float dx = dv * xv;
#pragma unroll
                for (int n = 0; n < 16; n++) {
                    float a = pw[n] * fmaf(dv, eps[n], 1.0f);
                    st[n] = fmaf(a, st[n], dx * Bv[n]);
                }
            }
            __syncwarp();
        }
    }

    // publish chunk summaries: cumulative factor = exp(negA_n * sum_delta)
#pragma unroll
    for (int n = 0; n < 16; n++) {
        float negAn = fmaf((float)(n + 1), negA0, eps[n]);
        sPA[(w * NS_ + n) * 32 + lane] = __expf(negAn * sdelta);
        sST[(w * NS_ + n) * 32 + lane] = st[n];
    }
    __syncthreads();

    // Phase B: block combine (thread = (d, n))
    {
        int cd = tid & 31;
        int cn = tid >> 5;
        float hacc = 0.0f;
#pragma unroll
        for (int wc = 0; wc < NCH; wc++) {
            int off = (wc * NS_ + cn) * 32 + cd;
            float pav = sPA[off];
            float stv = sST[off];
            sPA[off] = hacc;
            hacc = fmaf(pav, hacc, stv);
        }
    }
    __syncthreads();

    // Phase C: re-scan with correct init, emit output
#pragma unroll
    for (int n = 0; n < 16; n++) st[n] = sPA[(w * NS_ + n) * 32 + lane];

    {
        float pdl[4], pxv[4];
#pragma unroll
        for (int i = 0; i < 4; i++) {
            pdl[i] = delta[xbase + (size_t)i * D_];
            pxv[i] = h0[xbase + (size_t)i * D_];
        }
#pragma unroll
        for (int sub = 0; sub < CHL / SUBL; sub++) {
            float* bcw = sBC + (w * SUBL) * 32;
#pragma unroll 8
            for (int l = 0; l < SUBL; l++)
                bcw[l * 32 + lane] =
                    dbc[ebase + (size_t)(sub * SUBL + l) * E_];
            __syncwarp();

#pragma unroll 4
            for (int l = 0; l < SUBL; l++) {
                int gl = sub * SUBL + l;
                float dv = pdl[gl & 3];
                float xv = pxv[gl & 3];
                int lf = gl + 4;
                if (lf < CHL) {
                    pdl[gl & 3] = delta[xbase + (size_t)lf * D_];
                    pxv[gl & 3] = h0[xbase + (size_t)lf * D_];
                }

                float Bv[16], Cv[16];
                *(float4*)&Bv[0]  = *(const float4*)&bcw[l * 32 + 0];
                *(float4*)&Bv[4]  = *(const float4*)&bcw[l * 32 + 4];
                *(float4*)&Bv[8]  = *(const float4*)&bcw[l * 32 + 8];
                *(float4*)&Bv[12] = *(const float4*)&bcw[l * 32 + 12];
                *(float4*)&Cv[0]  = *(const float4*)&bcw[l * 32 + 16];
                *(float4*)&Cv[4]  = *(const float4*)&bcw[l * 32 + 20];
                *(float4*)&Cv[8]  = *(const float4*)&bcw[l * 32 + 24];
                *(float4*)&Cv[12] = *(const float4*)&bcw[l * 32 + 28];

                float p = __expf(dv * negA0);
                float p2 = p * p, p4 = p2 * p2, p8 = p4 * p4;
                float pw[16];
                pw[0] = p;          pw[1] = p2;         pw[2] = p2 * p;
                pw[3] = p4;         pw[4] = p4 * p;     pw[5] = p4 * p2;
                pw[6] = p4 * pw[2]; pw[7] = p8;
                pw[8] = p8 * p;     pw[9] = p8 * p2;    pw[10] = p8 * pw[2];
                pw[11] = p8 * p4;   pw[12] = p8 * pw[4]; pw[13] = p8 * pw[5];
                pw[14] = p8 * pw[6]; pw[15] = p8 * p8;

                float dx = dv * xv;
                float y0 = 0.f, y1 = 0.f, y2 = 0.f, y3 = 0.f;
#pragma unroll
                for (int n = 0; n < 16; n++) {
                    float a = pw[n] * fmaf(dv, eps[n], 1.0f);
                    st[n] = fmaf(a, st[n], dx * Bv[n]);
                    float yv = st[n] * Cv[n];
                    if ((n & 3) == 0) y0 += yv;
                    else if ((n & 3) == 1) y1 += yv;
                    else if ((n & 3) == 2) y2 += yv;
                    else y3 += yv;
                }
                float y = (y0 + y1) + (y2 + y3);
                hout[xbase + (size_t)gl * D_] = fmaf(xv, dp, xv + y);
            }
            __syncwarp();
        }
    }
}

// ---------------------------------------------------------------------------
// Launch
// ---------------------------------------------------------------------------
extern "C" void kernel_launch(void* const* d_in, const int* in_sizes, int n_in,
                              void* d_out, int out_size) {
    const float* x      = (const float*)d_in[0];
    const float* ln1_w  = (const float*)d_in[1];
    const float* ln2_w  = (const float*)d_in[2];
    const float* W_dbc  = (const float*)d_in[3];
    const float* W_dt   = (const float*)d_in[4];
    const float* b_dt   = (const float*)d_in[5];
    const float* A_log  = (const float*)d_in[6];
    const float* Dp     = (const float*)d_in[7];
    const float* W_fc   = (const float*)d_in[8];
    const float* W_proj = (const float*)d_in[9];
    float* out = (float*)d_out;

    float *h0, *dbc, *dbcp, *delta, *h;
    __nv_bfloat16 *h0h, *h0l, *wdbh, *wdbl;
    __half *m0f, *fcf, *wfcf, *wprf;
    cudaGetSymbolAddress((void**)&h0, g_h0);
    cudaGetSymbolAddress((void**)&dbc, g_dbc);
    cudaGetSymbolAddress((void**)&dbcp, g_dbcp);
    cudaGetSymbolAddress((void**)&delta, g_delta);
    cudaGetSymbolAddress((void**)&h, g_h);
    cudaGetSymbolAddress((void**)&h0h, g_h0h);
    cudaGetSymbolAddress((void**)&h0l, g_h0l);
    cudaGetSymbolAddress((void**)&wdbh, g_wdbh);
    cudaGetSymbolAddress((void**)&wdbl, g_wdbl);
    cudaGetSymbolAddress((void**)&m0f, g_m0f);
    cudaGetSymbolAddress((void**)&fcf, g_fcf);
    cudaGetSymbolAddress((void**)&wfcf, g_wfcf);
    cudaGetSymbolAddress((void**)&wprf, g_wprf);

    cudaFuncSetAttribute(gemm_hmma_kernel<1>,
                         cudaFuncAttributeMaxDynamicSharedMemorySize,
                         HSMEM_TOTAL);
    cudaFuncSetAttribute(gemm_hmma_kernel<2>,
                         cudaFuncAttributeMaxDynamicSharedMemorySize,
                         HSMEM_TOTAL);
    cudaFuncSetAttribute(gemm_dbc2_kernel,
                         cudaFuncAttributeMaxDynamicSharedMemorySize, S2TOT);
    cudaFuncSetAttribute(scan3_kernel,
                         cudaFuncAttributeMaxDynamicSharedMemorySize,
                         SC3_SMEM);

    // 1. h0 = softplus(ln1(x)) + W_dbc bf16 split + W_fc/W_proj fp16 converts
    ln1_mega_kernel<<<LN1_GRID, 256>>>(x, ln1_w, W_dbc, W_fc, W_proj, h0, h0h,
                                       h0l, wdbh, wdbl, wfcf, wprf);

    // 2. dbc partials: split-K x4 (M=4096, N=96, K=1024) [bf16 3-term WMMA]
    gemm_dbc2_kernel<<<dim3(ML_ / 128, 4), 256, S2TOT>>>(h0h, h0l, wdbh, wdbl,
                                                         dbcp);

    // 3. dbc = sum of partials (deterministic fixed order)
    dbcred_kernel<<<ML_ * E_ / 1024, 256>>>(dbcp, dbc);

    // 4. delta = softplus(dbc[:, :64] @ W_dt^T + b_dt)
    gemm_kernel<1, true><<<dim3(D_ / TBN, ML_ / TBM), 256>>>(
        dbc, E_, W_dt, R_, b_dt, delta, D_, ML_, D_, R_);

    // 5. h = h0 + ssm(h0)   [chunked block-parallel scan]
    scan3_kernel<<<dim3(D_ / 32, B_), 512, SC3_SMEM>>>(h0, delta, dbc, A_log,
                                                       Dp, h);

    // 6. m0 = ln2(h) -> fp16
    ln2_kernel<<<ML_, 256>>>(h, ln2_w, m0f);

    // 7. fc = gelu(m0 @ W_fc^T) -> fp16   (M=4096, N=4096, K=1024)
    gemm_hmma_kernel<1><<<dim3(F_ / 128, ML_ / 128), 256, HSMEM_TOTAL>>>(
        m0f, wfcf, D_, fcf, nullptr, nullptr, F_);

    // 8. out = h + fc @ W_proj^T   (M=4096, N=1024, K=4096)
    gemm_hmma_kernel<2><<<dim3(D_ / 128, ML_ / 128), 256, HSMEM_TOTAL>>>(
        fcf, wprf, F_, nullptr, out, h, D_);
}

// round 15
// speedup vs baseline: 1.0992x; 1.0310x over previous
#include <cuda_runtime.h>
#include <cuda_bf16.h>
#include <cuda_fp16.h>
#include <mma.h>
#include <math.h>
#include <stdint.h>

using namespace nvcuda;

// Shapes (fixed by the problem)
#define B_ 4
#define L_ 1024
#define D_ 1024
#define NS_ 16
#define R_ 64
#define E_ 96          // R + 2N
#define F_ 4096        // 4*D
#define ML_ (B_ * L_)  // 4096

// ---------------------------------------------------------------------------
// Scratch (no allocations allowed -> __device__ globals)
// ---------------------------------------------------------------------------
__device__ float g_h0[(size_t)ML_ * D_];       // softplus(ln1(x))
__device__ float g_dbc[(size_t)ML_ * E_];      // h0 @ W_dbc^T
__device__ float g_dbcp[4][(size_t)ML_ * E_];  // split-K partials
__device__ float g_delta[(size_t)ML_ * D_];    // softplus(dlr @ W_dt^T + b_dt)
__device__ float g_h[(size_t)ML_ * D_];        // h0 + ssm(h0)

// bf16 hi/lo splits (precision-sensitive tensor paths)
__device__ __nv_bfloat16 g_h0h[(size_t)ML_ * D_];
__device__ __nv_bfloat16 g_h0l[(size_t)ML_ * D_];
__device__ __nv_bfloat16 g_wdbh[(size_t)E_ * D_];
__device__ __nv_bfloat16 g_wdbl[(size_t)E_ * D_];
__device__ __nv_bfloat16 g_dlrh[(size_t)ML_ * R_];
__device__ __nv_bfloat16 g_dlrl[(size_t)ML_ * R_];
__device__ __nv_bfloat16 g_wdth[(size_t)D_ * R_];
__device__ __nv_bfloat16 g_wdtl[(size_t)D_ * R_];

// fp16 single operands for the two big GEMMs
__device__ __half g_m0f[(size_t)ML_ * D_];
__device__ __half g_fcf[(size_t)ML_ * F_];
__device__ __half g_wfcf[(size_t)F_ * D_];
__device__ __half g_wprf[(size_t)D_ * F_];

// ---------------------------------------------------------------------------
// Activations
// ---------------------------------------------------------------------------
__device__ __forceinline__ float softplus_f(float v) {
    return fmaxf(v, 0.0f) + log1pf(__expf(-fabsf(v)));
}
__device__ __forceinline__ float gelu_f(float v) {
    const float c = 0.7978845608028654f;
    float v3 = v * v * v;
    return 0.5f * v * (1.0f + tanhf(c * (v + 0.044715f * v3)));
}

// ---------------------------------------------------------------------------
// PTX helpers
// ---------------------------------------------------------------------------
__device__ __forceinline__ uint32_t smem_u32(const void* p) {
    uint32_t a;
    asm("{ .reg .u64 t; cvta.to.shared.u64 t, %1; cvt.u32.u64 %0, t; }"
        : "=r"(a) : "l"(p));
    return a;
}
__device__ __forceinline__ void cp_async8(uint32_t dst, const void* src) {
    asm volatile("cp.async.ca.shared.global [%0], [%1], 8;\n"
                 :: "r"(dst), "l"(src));
}
__device__ __forceinline__ void cp_commit() {
    asm volatile("cp.async.commit_group;\n" ::: "memory");
}
template <int N>
__device__ __forceinline__ void cp_wait() {
    asm volatile("cp.async.wait_group %0;\n" :: "n"(N) : "memory");
}

// ---------------------------------------------------------------------------
// Big HMMA fp16 GEMM (R9 config): CTA 128x128, BK=64, 8 warps (4x2),
// warp tile 32x64, double-buffered cp.async.
// EPI==1: C = gelu(acc) -> fp16 Ch.   EPI==2: C = acc + addv -> fp32 Cf.
// ---------------------------------------------------------------------------
#define HPAD 72                      // halves per row (64 + 8); 144B stride
#define HTILE_B (128 * HPAD * 2)     // 18432 bytes
#define HSTG_B (2 * HTILE_B)         // 36864 bytes per stage (A + B)
#define HSMEM_TOTAL (2 * HSTG_B)     // 73728 bytes (>= 64KB epilogue staging)

template <int EPI>
__global__ __launch_bounds__(256) void gemm_hmma_kernel(
    const __half* __restrict__ A, const __half* __restrict__ Bm, int K,
    __half* __restrict__ Ch, float* __restrict__ Cf,
    const float* __restrict__ addv, int ldc) {
    extern __shared__ char dsm[];
    int tid = threadIdx.x;
    int wid = tid >> 5;
    int wm = wid >> 1;
    int wn = wid & 1;
    int bm = blockIdx.y * 128;
    int bn = blockIdx.x * 128;

    wmma::fragment<wmma::accumulator, 16, 16, 16, float> acc[2][4];
#pragma unroll
    for (int i = 0; i < 2; i++)
#pragma unroll
        for (int j = 0; j < 4; j++) wmma::fill_fragment(acc[i][j], 0.0f);

    auto load_chunk = [&](int st, int kc) {
        uint32_t sb = smem_u32(dsm) + st * HSTG_B;
        int k0 = kc * 64;
#pragma unroll
        for (int j = 0; j < 8; j++) {
            int idx = tid + j * 256;   // 0..2047
            int r = idx >> 4;          // 0..127
            int g = idx & 15;          // 16 groups of 4 halves
            uint32_t so = (uint32_t)(r * (HPAD * 2) + g * 8);
            cp_async8(sb + so, A + (size_t)(bm + r) * K + k0 + g * 4);
            cp_async8(sb + HTILE_B + so,
                      Bm + (size_t)(bn + r) * K + k0 + g * 4);
        }
    };

    const int NC = K / 64;
    load_chunk(0, 0);
    cp_commit();

    for (int kc = 0; kc < NC; kc++) {
        int st = kc & 1;
        if (kc + 1 < NC) {
            load_chunk(st ^ 1, kc + 1);
            cp_commit();
            cp_wait<1>();
        } else {
            cp_wait<0>();
        }
        __syncthreads();

        const __half* sA = (const __half*)(dsm + st * HSTG_B);
        const __half* sB = (const __half*)(dsm + st * HSTG_B + HTILE_B);

#pragma unroll
        for (int kk = 0; kk < 64; kk += 16) {
            wmma::fragment<wmma::matrix_a, 16, 16, 16, __half,
                           wmma::row_major> fa[2];
            wmma::fragment<wmma::matrix_b, 16, 16, 16, __half,
                           wmma::col_major> fb[4];
#pragma unroll
            for (int i = 0; i < 2; i++)
                wmma::load_matrix_sync(fa[i],
                                       sA + (wm * 32 + i * 16) * HPAD + kk,
                                       HPAD);
#pragma unroll
            for (int j = 0; j < 4; j++)
                wmma::load_matrix_sync(fb[j],
                                       sB + (wn * 64 + j * 16) * HPAD + kk,
                                       HPAD);
#pragma unroll
            for (int i = 0; i < 2; i++)
#pragma unroll
                for (int j = 0; j < 4; j++)
                    wmma::mma_sync(acc[i][j], fa[i], fb[j], acc[i][j]);
        }
        __syncthreads();
    }

    // Epilogue via smem fp32 staging tile for coalesced writes
    float* sC = (float*)dsm;
#pragma unroll
    for (int i = 0; i < 2; i++)
#pragma unroll
        for (int j = 0; j < 4; j++)
            wmma::store_matrix_sync(sC + (wm * 32 + i * 16) * 128 +
                                        (wn * 64 + j * 16),
                                    acc[i][j], 128, wmma::mem_row_major);
    __syncthreads();

#pragma unroll
    for (int it = 0; it < 16; it++) {
        int idx = tid + it * 256;
        int r = idx >> 5;
        int c4 = idx & 31;
        float4 v = ((const float4*)(sC + r * 128))[c4];
        size_t row = bm + r;
        size_t col = bn + c4 * 4;
        if (EPI == 1) {
            __half o[4];
            o[0] = __float2half(gelu_f(v.x));
            o[1] = __float2half(gelu_f(v.y));
            o[2] = __float2half(gelu_f(v.z));
            o[3] = __float2half(gelu_f(v.w));
            *(uint2*)(Ch + row * ldc + col) = *(uint2*)o;
        } else {
            const float4 av = *(const float4*)(addv + row * ldc + col);
            *(float4*)(Cf + row * ldc + col) =
                make_float4(v.x + av.x, v.y + av.y, v.z + av.z, v.w + av.w);
        }
    }
}

// ---------------------------------------------------------------------------
// dbc split-K: C_partial[kz][4096,96] = Ah/Al[:,kz*256:+256] @ B^T slice.
// Grid (32, 4). bf16 3-term compensation.
// ---------------------------------------------------------------------------
#define S2PAD 36
#define S2A (128 * S2PAD * 2)
#define S2B (96 * S2PAD * 2)
#define S2STG (2 * S2A + 2 * S2B)
#define S2TOT (2 * S2STG)

__global__ __launch_bounds__(256) void gemm_dbc2_kernel(
    const __nv_bfloat16* __restrict__ Ah, const __nv_bfloat16* __restrict__ Al,
    const __nv_bfloat16* __restrict__ Bh, const __nv_bfloat16* __restrict__ Bl,
    float* __restrict__ P) {
    extern __shared__ char dsm[];
    int tid = threadIdx.x;
    int wid = tid >> 5;
    int bm = blockIdx.x * 128;
    int kz = blockIdx.y;
    const int K = D_;
    const int k0base = kz * 256;
    float* C = P + (size_t)kz * ML_ * E_;

    wmma::fragment<wmma::accumulator, 16, 16, 16, float> acc[6];
#pragma unroll
    for (int j = 0; j < 6; j++) wmma::fill_fragment(acc[j], 0.0f);

    auto load_chunk = [&](int st, int kc) {
        uint32_t sb = smem_u32(dsm) + st * S2STG;
        int k0 = k0base + kc * 32;
#pragma unroll
        for (int j = 0; j < 4; j++) {
            int idx = tid + j * 256;
            int r = idx >> 3, cg = idx & 7;
            uint32_t so = (uint32_t)(r * (S2PAD * 2) + cg * 8);
            size_t ao = (size_t)(bm + r) * K + k0 + cg * 4;
            cp_async8(sb + so, Ah + ao);
            cp_async8(sb + S2A + so, Al + ao);
        }
#pragma unroll
        for (int j = 0; j < 3; j++) {
            int idx = tid + j * 256;
            int r = idx >> 3, cg = idx & 7;
            uint32_t so = (uint32_t)(r * (S2PAD * 2) + cg * 8);
            size_t bo = (size_t)r * K + k0 + cg * 4;
            cp_async8(sb + 2 * S2A + so, Bh + bo);
            cp_async8(sb + 2 * S2A + S2B + so, Bl + bo);
        }
    };

    const int NC = 8;
    load_chunk(0, 0);
    cp_commit();

    for (int kc = 0; kc < NC; kc++) {
        int st = kc & 1;
        if (kc + 1 < NC) {
            load_chunk(st ^ 1, kc + 1);
            cp_commit();
            cp_wait<1>();
        } else {
            cp_wait<0>();
        }
        __syncthreads();

        const __nv_bfloat16* sAh = (const __nv_bfloat16*)(dsm + st * S2STG);
        const __nv_bfloat16* sAl =
            (const __nv_bfloat16*)(dsm + st * S2STG + S2A);
        const __nv_bfloat16* sBh =
            (const __nv_bfloat16*)(dsm + st * S2STG + 2 * S2A);
        const __nv_bfloat16* sBl =
            (const __nv_bfloat16*)(dsm + st * S2STG + 2 * S2A + S2B);

#pragma unroll
        for (int kk = 0; kk < 32; kk += 16) {
            wmma::fragment<wmma::matrix_a, 16, 16, 16, __nv_bfloat16,
                           wmma::row_major> fah, fal;
            wmma::fragment<wmma::matrix_b, 16, 16, 16, __nv_bfloat16,
                           wmma::col_major> fbh[6], fbl[6];
            int r0 = wid * 16;
            wmma::load_matrix_sync(fah, sAh + r0 * S2PAD + kk, S2PAD);
            wmma::load_matrix_sync(fal, sAl + r0 * S2PAD + kk, S2PAD);
#pragma unroll
            for (int j = 0; j < 6; j++) {
                wmma::load_matrix_sync(fbh[j], sBh + j * 16 * S2PAD + kk,
                                       S2PAD);
                wmma::load_matrix_sync(fbl[j], sBl + j * 16 * S2PAD + kk,
                                       S2PAD);
            }
#pragma unroll
            for (int j = 0; j < 6; j++) {
                wmma::mma_sync(acc[j], fah, fbh[j], acc[j]);
                wmma::mma_sync(acc[j], fal, fbh[j], acc[j]);
                wmma::mma_sync(acc[j], fah, fbl[j], acc[j]);
            }
        }
        __syncthreads();
    }

    float* sC = (float*)dsm;
#pragma unroll
    for (int j = 0; j < 6; j++)
        wmma::store_matrix_sync(sC + (wid * 16) * 96 + j * 16, acc[j], 96,
                                wmma::mem_row_major);
    __syncthreads();

#pragma unroll
    for (int it = 0; it < 12; it++) {
        int idx = tid + it * 256;
        int r = idx / 24;
        int c4 = idx % 24;
        float4 v = ((const float4*)sC)[idx];
        *(float4*)(C + (size_t)(bm + r) * E_ + c4 * 4) = v;
    }
}

// Deterministic fixed-order reduce of 4 split-K partials.
// Also emits dlr (= dbc[:, 0:64]) as bf16 hi/lo for the delta HMMA GEMM.
__global__ __launch_bounds__(256) void dbcred_kernel(
    const float* __restrict__ P, float* __restrict__ C,
    __nv_bfloat16* __restrict__ dlrh, __nv_bfloat16* __restrict__ dlrl) {
    int i = blockIdx.x * 256 + threadIdx.x;  // float4 index < 98304
    const size_t stride = (size_t)ML_ * E_ / 4;
    const float4* p = (const float4*)P;
    float4 a = p[i];
    float4 b = p[stride + i];
    float4 c = p[2 * stride + i];
    float4 d = p[3 * stride + i];
    float4 o = make_float4(((a.x + b.x) + (c.x + d.x)),
                           ((a.y + b.y) + (c.y + d.y)),
                           ((a.z + b.z) + (c.z + d.z)),
                           ((a.w + b.w) + (c.w + d.w)));
    ((float4*)C)[i] = o;
    int r = i / 24;
    int c4 = i % 24;
    if (c4 < 16) {  // cols < 64 -> dlr path
        float vv[4] = {o.x, o.y, o.z, o.w};
        __nv_bfloat16 h[4], l[4];
#pragma unroll
        for (int j = 0; j < 4; j++) {
            h[j] = __float2bfloat16(vv[j]);
            l[j] = __float2bfloat16(vv[j] - __bfloat162float(h[j]));
        }
        ((uint2*)dlrh)[r * 16 + c4] = *(uint2*)h;
        ((uint2*)dlrl)[r * 16 + c4] = *(uint2*)l;
    }
}

// ---------------------------------------------------------------------------
// delta HMMA GEMM: delta[4096,1024] = softplus(dlr @ W_dt^T + b_dt)
// bf16 3-term, K=64 single-shot (no pipeline). CTA 128x128, 8 warps (4x2).
// ---------------------------------------------------------------------------
#define DT_TILE (128 * HPAD * 2)   // 18432 bytes (K=64 + pad rows)
#define DSMEM (4 * DT_TILE)        // 73728 bytes (>= 64KB epilogue staging)

__global__ __launch_bounds__(256) void gemm_delta_kernel(
    const __nv_bfloat16* __restrict__ Ah, const __nv_bfloat16* __restrict__ Al,
    const __nv_bfloat16* __restrict__ Bh, const __nv_bfloat16* __restrict__ Bl,
    const float* __restrict__ bias, float* __restrict__ C) {
    extern __shared__ char dsm[];
    int tid = threadIdx.x;
    int wid = tid >> 5;
    int wm = wid >> 1;
    int wn = wid & 1;
    int bm = blockIdx.y * 128;
    int bn = blockIdx.x * 128;

    // Load all four 128x64 bf16 tiles (Ah, Al, Bh, Bl)
    {
        uint32_t sb = smem_u32(dsm);
#pragma unroll
        for (int j = 0; j < 8; j++) {
            int idx = tid + j * 256;   // 0..2047
            int r = idx >> 4;          // 0..127
            int g = idx & 15;          // groups of 4 halves
            uint32_t so = (uint32_t)(r * (HPAD * 2) + g * 8);
            size_t ao = (size_t)(bm + r) * R_ + g * 4;
            size_t bo = (size_t)(bn + r) * R_ + g * 4;
            cp_async8(sb + so, Ah + ao);
            cp_async8(sb + DT_TILE + so, Al + ao);
            cp_async8(sb + 2 * DT_TILE + so, Bh + bo);
            cp_async8(sb + 3 * DT_TILE + so, Bl + bo);
        }
        cp_commit();
        cp_wait<0>();
        __syncthreads();
    }

    const __nv_bfloat16* sAh = (const __nv_bfloat16*)dsm;
    const __nv_bfloat16* sAl = (const __nv_bfloat16*)(dsm + DT_TILE);
    const __nv_bfloat16* sBh = (const __nv_bfloat16*)(dsm + 2 * DT_TILE);
    const __nv_bfloat16* sBl = (const __nv_bfloat16*)(dsm + 3 * DT_TILE);

    wmma::fragment<wmma::accumulator, 16, 16, 16, float> acc[2][4];
#pragma unroll
    for (int i = 0; i < 2; i++)
#pragma unroll
        for (int j = 0; j < 4; j++) wmma::fill_fragment(acc[i][j], 0.0f);

#pragma unroll
    for (int kk = 0; kk < 64; kk += 16) {
        wmma::fragment<wmma::matrix_a, 16, 16, 16, __nv_bfloat16,
                       wmma::row_major> fah[2], fal[2];
        wmma::fragment<wmma::matrix_b, 16, 16, 16, __nv_bfloat16,
                       wmma::col_major> fbh[4], fbl[4];
#pragma unroll
        for (int i = 0; i < 2; i++) {
            int r0 = wm * 32 + i * 16;
            wmma::load_matrix_sync(fah[i], sAh + r0 * HPAD + kk, HPAD);
            wmma::load_matrix_sync(fal[i], sAl + r0 * HPAD + kk, HPAD);
        }
#pragma unroll
        for (int j = 0; j < 4; j++) {
            int c0 = wn * 64 + j * 16;
            wmma::load_matrix_sync(fbh[j], sBh + c0 * HPAD + kk, HPAD);
            wmma::load_matrix_sync(fbl[j], sBl + c0 * HPAD + kk, HPAD);
        }
#pragma unroll
        for (int i = 0; i < 2; i++)
#pragma unroll
            for (int j = 0; j < 4; j++) {
                wmma::mma_sync(acc[i][j], fah[i], fbh[j], acc[i][j]);
                wmma::mma_sync(acc[i][j], fal[i], fbh[j], acc[i][j]);
                wmma::mma_sync(acc[i][j], fah[i], fbl[j], acc[i][j]);
            }
    }
    __syncthreads();

    float* sC = (float*)dsm;
#pragma unroll
    for (int i = 0; i < 2; i++)
#pragma unroll
        for (int j = 0; j < 4; j++)
            wmma::store_matrix_sync(sC + (wm * 32 + i * 16) * 128 +
                                        (wn * 64 + j * 16),
                                    acc[i][j], 128, wmma::mem_row_major);
    __syncthreads();

#pragma unroll
    for (int it = 0; it < 16; it++) {
        int idx = tid + it * 256;
        int r = idx >> 5;
        int c4 = idx & 31;
        float4 v = ((const float4*)(sC + r * 128))[c4];
        size_t row = bm + r;
        size_t col = bn + c4 * 4;
        const float4 bv = *(const float4*)(bias + col);
        float4 o = make_float4(softplus_f(v.x + bv.x), softplus_f(v.y + bv.y),
                               softplus_f(v.z + bv.z), softplus_f(v.w + bv.w));
        *(float4*)(C + row * D_ + col) = o;
    }
}

// ---------------------------------------------------------------------------
// ln1 mega-fused. Block ranges:
//  [0, ML_)                      : softplus(ln(x)) -> fp32 + bf16 hi/lo
//  [ML_, +96)                    : W_dbc -> bf16 hi/lo
//  [ML_+96, +4096)               : W_fc -> fp16
//  [ML_+4192, +4096)             : W_proj -> fp16
//  [ML_+8288, +64)               : W_dt -> bf16 hi/lo
// ---------------------------------------------------------------------------
#define LN1_GRID (ML_ + 96 + 4096 + 4096 + 64)

__global__ __launch_bounds__(256) void ln1_mega_kernel(
    const float* __restrict__ x, const float* __restrict__ w,
    const float* __restrict__ W_dbc, const float* __restrict__ W_fc,
    const float* __restrict__ W_proj, const float* __restrict__ W_dt,
    float* __restrict__ out, __nv_bfloat16* __restrict__ oh,
    __nv_bfloat16* __restrict__ ol,
    __nv_bfloat16* __restrict__ wdh, __nv_bfloat16* __restrict__ wdl,
    __half* __restrict__ wfcf, __half* __restrict__ wprf,
    __nv_bfloat16* __restrict__ wdth, __nv_bfloat16* __restrict__ wdtl) {
    __shared__ float red[8];
    int bid = blockIdx.x;
    int t = threadIdx.x;

    if (bid >= ML_) {
        int r = bid - ML_;
        if (r < 96) {  // W_dbc bf16 hi/lo split
            int i = r * 256 + t;
            float4 v = ((const float4*)W_dbc)[i];
            float vv[4] = {v.x, v.y, v.z, v.w};
            __nv_bfloat16 h[4], l[4];
#pragma unroll
            for (int j = 0; j < 4; j++) {
                h[j] = __float2bfloat16(vv[j]);
                l[j] = __float2bfloat16(vv[j] - __bfloat162float(h[j]));
            }
            ((uint2*)wdh)[i] = *(uint2*)h;
            ((uint2*)wdl)[i] = *(uint2*)l;
        } else if (r < 96 + 4096) {  // W_fc -> fp16
            int i = (r - 96) * 256 + t;
            float4 v = ((const float4*)W_fc)[i];
            __half h[4] = {__float2half(v.x), __float2half(v.y),
                           __float2half(v.z), __float2half(v.w)};
            ((uint2*)wfcf)[i] = *(uint2*)h;
        } else if (r < 96 + 8192) {  // W_proj -> fp16
            int i = (r - 96 - 4096) * 256 + t;
            float4 v = ((const float4*)W_proj)[i];
            __half h[4] = {__float2half(v.x), __float2half(v.y),
                           __float2half(v.z), __float2half(v.w)};
            ((uint2*)wprf)[i] = *(uint2*)h;
        } else {  // W_dt bf16 hi/lo split (16384 float4)
            int i = (r - 96 - 8192) * 256 + t;
            float4 v = ((const float4*)W_dt)[i];
            float vv[4] = {v.x, v.y, v.z, v.w};
            __nv_bfloat16 h[4], l[4];
#pragma unroll
            for (int j = 0; j < 4; j++) {
                h[j] = __float2bfloat16(vv[j]);
                l[j] = __float2bfloat16(vv[j] - __bfloat162float(h[j]));
            }
            ((uint2*)wdth)[i] = *(uint2*)h;
            ((uint2*)wdtl)[i] = *(uint2*)l;
        }
        return;
    }

    int row = bid;
    const float4* xr = (const float4*)(x + (size_t)row * D_);
    float4 v = xr[t];

    float s = v.x + v.y + v.z + v.w;
#pragma unroll
    for (int m = 16; m > 0; m >>= 1) s += __shfl_xor_sync(0xffffffffu, s, m);
    if ((t & 31) == 0) red[t >> 5] = s;
    __syncthreads();
    float tot = 0.0f;
#pragma unroll
    for (int i = 0; i < 8; i++) tot += red[i];
    float mu = tot * (1.0f / D_);

    float cx = v.x - mu, cy = v.y - mu, cz = v.z - mu, cw = v.w - mu;
    float s2 = cx * cx + cy * cy + cz * cz + cw * cw;
#pragma unroll
    for (int m = 16; m > 0; m >>= 1) s2 += __shfl_xor_sync(0xffffffffu, s2, m);
    __syncthreads();
    if ((t & 31) == 0) red[t >> 5] = s2;
    __syncthreads();
    float tot2 = 0.0f;
#pragma unroll
    for (int i = 0; i < 8; i++) tot2 += red[i];
    float rs = rsqrtf(tot2 * (1.0f / D_) + 1e-5f);

    float4 wv = ((const float4*)w)[t];
    float o[4];
    o[0] = softplus_f(cx * rs * wv.x);
    o[1] = softplus_f(cy * rs * wv.y);
    o[2] = softplus_f(cz * rs * wv.z);
    o[3] = softplus_f(cw * rs * wv.w);
    ((float4*)(out + (size_t)row * D_))[t] = make_float4(o[0], o[1], o[2], o[3]);

    __nv_bfloat16 h[4], l[4];
#pragma unroll
    for (int j = 0; j < 4; j++) {
        h[j] = __float2bfloat16(o[j]);
        l[j] = __float2bfloat16(o[j] - __bfloat162float(h[j]));
    }
    ((uint2*)(oh + (size_t)row * D_))[t] = *(uint2*)h;
    ((uint2*)(ol + (size_t)row * D_))[t] = *(uint2*)l;
}

// ---------------------------------------------------------------------------
// ln2: ln(h) -> fp16 single
// ---------------------------------------------------------------------------
__global__ __launch_bounds__(256) void ln2_kernel(const float* __restrict__ x,
                                                  const float* __restrict__ w,
                                                  __half* __restrict__ o16) {
    int row = blockIdx.x;
    int t = threadIdx.x;
    __shared__ float red[8];

    const float4* xr = (const float4*)(x + (size_t)row * D_);
    float4 v = xr[t];

    float s = v.x + v.y + v.z + v.w;
#pragma unroll
    for (int m = 16; m > 0; m >>= 1) s += __shfl_xor_sync(0xffffffffu, s, m);
    if ((t & 31) == 0) red[t >> 5] = s;
    __syncthreads();
    float tot = 0.0f;
#pragma unroll
    for (int i = 0; i < 8; i++) tot += red[i];
    float mu = tot * (1.0f / D_);

    float cx = v.x - mu, cy = v.y - mu, cz = v.z - mu, cw = v.w - mu;
    float s2 = cx * cx + cy * cy + cz * cz + cw * cw;
#pragma unroll
    for (int m = 16; m > 0; m >>= 1) s2 += __shfl_xor_sync(0xffffffffu, s2, m);
    __syncthreads();
    if ((t & 31) == 0) red[t >> 5] = s2;
    __syncthreads();
    float tot2 = 0.0f;
#pragma unroll
    for (int i = 0; i < 8; i++) tot2 += red[i];
    float rs = rsqrtf(tot2 * (1.0f / D_) + 1e-5f);

    float4 wv = ((const float4*)w)[t];
    __half h[4];
    h[0] = __float2half(cx * rs * wv.x);
    h[1] = __float2half(cy * rs * wv.y);
    h[2] = __float2half(cz * rs * wv.z);
    h[3] = __float2half(cw * rs * wv.w);
    ((uint2*)(o16 + (size_t)row * D_))[t] = *(uint2*)h;
}

// ---------------------------------------------------------------------------
// Selective scan v3.1: block-local chunked parallel scan (unchanged from R14)
// ---------------------------------------------------------------------------
#define NCH 16
#define CHL 64
#define SUBL 32

#define SC3_BC 0
#define SC3_PA 65536
#define SC3_ST 98304
#define SC3_SMEM 131072

__global__ __launch_bounds__(512) void scan3_kernel(
    const float* __restrict__ h0, const float* __restrict__ delta,
    const float* __restrict__ dbc, const float* __restrict__ A_log,
    const float* __restrict__ Dp, float* __restrict__ hout) {
    extern __shared__ char dsm[];
    float* sBC = (float*)(dsm + SC3_BC);
    float* sPA = (float*)(dsm + SC3_PA);
    float* sST = (float*)(dsm + SC3_ST);

    int tid = threadIdx.x;
    int lane = tid & 31;
    int w = tid >> 5;
    int d = blockIdx.x * 32 + lane;
    int b = blockIdx.y;

    float negA0 = -__expf(A_log[d * NS_]);
    float eps[16];
#pragma unroll
    for (int n = 0; n < 16; n++)
        eps[n] = -__expf(A_log[d * NS_ + n]) - (float)(n + 1) * negA0;
    float dp = Dp[d];

    size_t xbase = ((size_t)b * L_ + (size_t)w * CHL) * D_ + d;
    size_t ebase = ((size_t)b * L_ + (size_t)w * CHL) * E_ + R_ + lane;

    float st[16];
#pragma unroll
    for (int n = 0; n < 16; n++) st[n] = 0.0f;
    float sdelta = 0.0f;

    // Phase A: local scan from zero state + sum of deltas
    {
        float pdl[4], pxv[4];
#pragma unroll
        for (int i = 0; i < 4; i++) {
            pdl[i] = delta[xbase + (size_t)i * D_];
            pxv[i] = h0[xbase + (size_t)i * D_];
        }
#pragma unroll
        for (int sub = 0; sub < CHL / SUBL; sub++) {
            float* bcw = sBC + (w * SUBL) * 32;
#pragma unroll 8
            for (int l = 0; l < SUBL; l++)
                bcw[l * 32 + lane] =
                    dbc[ebase + (size_t)(sub * SUBL + l) * E_];
            __syncwarp();

#pragma unroll 4
            for (int l = 0; l < SUBL; l++) {
                int gl = sub * SUBL + l;
                float dv = pdl[gl & 3];
                float xv = pxv[gl & 3];
                int lf = gl + 4;
                if (lf < CHL) {
                    pdl[gl & 3] = delta[xbase + (size_t)lf * D_];
                    pxv[gl & 3] = h0[xbase + (size_t)lf * D_];
                }

                float Bv[16];
                *(float4*)&Bv[0]  = *(const float4*)&bcw[l * 32 + 0];
                *(float4*)&Bv[4]  = *(const float4*)&bcw[l * 32 + 4];
                *(float4*)&Bv[8]  = *(const float4*)&bcw[l * 32 + 8];
                *(float4*)&Bv[12] = *(const float4*)&bcw[l * 32 + 12];

                float p = __expf(dv * negA0);
                float p2 = p * p, p4 = p2 * p2, p8 = p4 * p4;
                float pw[16];
                pw[0] = p;          pw[1] = p2;         pw[2] = p2 * p;
                pw[3] = p4;         pw[4] = p4 * p;     pw[5] = p4 * p2;
                pw[6] = p4 * pw[2]; pw[7] = p8;
                pw[8] = p8 * p;     pw[9] = p8 * p2;    pw[10] = p8 * pw[2];
                pw[11] = p8 * p4;   pw[12] = p8 * pw[4]; pw[13] = p8 * pw[5];
                pw[14] = p8 * pw[6]; pw[15] = p8 * p8;

                sdelta += dv;
                float dx = dv * xv;
#pragma unroll
                for (int n = 0; n < 16; n++) {
                    float a = pw[n] * fmaf(dv, eps[n], 1.0f);
                    st[n] = fmaf(a, st[n], dx * Bv[n]);
                }
            }
            __syncwarp();
        }
    }

    // publish chunk summaries
#pragma unroll
    for (int n = 0; n < 16; n++) {
        float negAn = fmaf((float)(n + 1), negA0, eps[n]);
        sPA[(w * NS_ + n) * 32 + lane] = __expf(negAn * sdelta);
        sST[(w * NS_ + n) * 32 + lane] = st[n];
    }
    __syncthreads();

    // Phase B: block combine
    {
        int cd = tid & 31;
        int cn = tid >> 5;
        float hacc = 0.0f;
#pragma unroll
        for (int wc = 0; wc < NCH; wc++) {
            int off = (wc * NS_ + cn) * 32 + cd;
            float pav = sPA[off];
            float stv = sST[off];
            sPA[off] = hacc;
            hacc = fmaf(pav, hacc, stv);
        }
    }
    __syncthreads();

    // Phase C: re-scan with correct init, emit output
#pragma unroll
    for (int n = 0; n < 16; n++) st[n] = sPA[(w * NS_ + n) * 32 + lane];

    {
        float pdl[4], pxv[4];
#pragma unroll
        for (int i = 0; i < 4; i++) {
            pdl[i] = delta[xbase + (size_t)i * D_];
            pxv[i] = h0[xbase + (size_t)i * D_];
        }
#pragma unroll
        for (int sub = 0; sub < CHL / SUBL; sub++) {
            float* bcw = sBC + (w * SUBL) * 32;
#pragma unroll 8
            for (int l = 0; l < SUBL; l++)
                bcw[l * 32 + lane] =
                    dbc[ebase + (size_t)(sub * SUBL + l) * E_];
            __syncwarp();

#pragma unroll 4
            for (int l = 0; l < SUBL; l++) {
                int gl = sub * SUBL + l;
                float dv = pdl[gl & 3];
                float xv = pxv[gl & 3];
                int lf = gl + 4;
                if (lf < CHL) {
                    pdl[gl & 3] = delta[xbase + (size_t)lf * D_];
                    pxv[gl & 3] = h0[xbase + (size_t)lf * D_];
                }

                float Bv[16], Cv[16];
                *(float4*)&Bv[0]  = *(const float4*)&bcw[l * 32 + 0];
                *(float4*)&Bv[4]  = *(const float4*)&bcw[l * 32 + 4];
                *(float4*)&Bv[8]  = *(const float4*)&bcw[l * 32 + 8];
                *(float4*)&Bv[12] = *(const float4*)&bcw[l * 32 + 12];
                *(float4*)&Cv[0]  = *(const float4*)&bcw[l * 32 + 16];
                *(float4*)&Cv[4]  = *(const float4*)&bcw[l * 32 + 20];
                *(float4*)&Cv[8]  = *(const float4*)&bcw[l * 32 + 24];
                *(float4*)&Cv[12] = *(const float4*)&bcw[l * 32 + 28];

                float p = __expf(dv * negA0);
                float p2 = p * p, p4 = p2 * p2, p8 = p4 * p4;
                float pw[16];
                pw[0] = p;          pw[1] = p2;         pw[2] = p2 * p;
                pw[3] = p4;         pw[4] = p4 * p;     pw[5] = p4 * p2;
                pw[6] = p4 * pw[2]; pw[7] = p8;
                pw[8] = p8 * p;     pw[9] = p8 * p2;    pw[10] = p8 * pw[2];
                pw[11] = p8 * p4;   pw[12] = p8 * pw[4]; pw[13] = p8 * pw[5];
                pw[14] = p8 * pw[6]; pw[15] = p8 * p8;

                float dx = dv * xv;
                float y0 = 0.f, y1 = 0.f, y2 = 0.f, y3 = 0.f;
#pragma unroll
                for (int n = 0; n < 16; n++) {
                    float a = pw[n] * fmaf(dv, eps[n], 1.0f);
                    st[n] = fmaf(a, st[n], dx * Bv[n]);
                    float yv = st[n] * Cv[n];
                    if ((n & 3) == 0) y0 += yv;
                    else if ((n & 3) == 1) y1 += yv;
                    else if ((n & 3) == 2) y2 += yv;
                    else y3 += yv;
                }
                float y = (y0 + y1) + (y2 + y3);
                hout[xbase + (size_t)gl * D_] = fmaf(xv, dp, xv + y);
            }
            __syncwarp();
        }
    }
}

// ---------------------------------------------------------------------------
// Launch
// ---------------------------------------------------------------------------
extern "C" void kernel_launch(void* const* d_in, const int* in_sizes, int n_in,
                              void* d_out, int out_size) {
    const float* x      = (const float*)d_in[0];
    const float* ln1_w  = (const float*)d_in[1];
    const float* ln2_w  = (const float*)d_in[2];
    const float* W_dbc  = (const float*)d_in[3];
    const float* W_dt   = (const float*)d_in[4];
    const float* b_dt   = (const float*)d_in[5];
    const float* A_log  = (const float*)d_in[6];
    const float* Dp     = (const float*)d_in[7];
    const float* W_fc   = (const float*)d_in[8];
    const float* W_proj = (const float*)d_in[9];
    float* out = (float*)d_out;

    float *h0, *dbc, *dbcp, *delta, *h;
    __nv_bfloat16 *h0h, *h0l, *wdbh, *wdbl, *dlrh, *dlrl, *wdth, *wdtl;
    __half *m0f, *fcf, *wfcf, *wprf;
    cudaGetSymbolAddress((void**)&h0, g_h0);
    cudaGetSymbolAddress((void**)&dbc, g_dbc);
    cudaGetSymbolAddress((void**)&dbcp, g_dbcp);
    cudaGetSymbolAddress((void**)&delta, g_delta);
    cudaGetSymbolAddress((void**)&h, g_h);
    cudaGetSymbolAddress((void**)&h0h, g_h0h);
    cudaGetSymbolAddress((void**)&h0l, g_h0l);
    cudaGetSymbolAddress((void**)&wdbh, g_wdbh);
    cudaGetSymbolAddress((void**)&wdbl, g_wdbl);
    cudaGetSymbolAddress((void**)&dlrh, g_dlrh);
    cudaGetSymbolAddress((void**)&dlrl, g_dlrl);
    cudaGetSymbolAddress((void**)&wdth, g_wdth);
    cudaGetSymbolAddress((void**)&wdtl, g_wdtl);
    cudaGetSymbolAddress((void**)&m0f, g_m0f);
    cudaGetSymbolAddress((void**)&fcf, g_fcf);
    cudaGetSymbolAddress((void**)&wfcf, g_wfcf);
    cudaGetSymbolAddress((void**)&wprf, g_wprf);

    cudaFuncSetAttribute(gemm_hmma_kernel<1>,
                         cudaFuncAttributeMaxDynamicSharedMemorySize,
                         HSMEM_TOTAL);
    cudaFuncSetAttribute(gemm_hmma_kernel<2>,
                         cudaFuncAttributeMaxDynamicSharedMemorySize,
                         HSMEM_TOTAL);
    cudaFuncSetAttribute(gemm_dbc2_kernel,
                         cudaFuncAttributeMaxDynamicSharedMemorySize, S2TOT);
    cudaFuncSetAttribute(gemm_delta_kernel,
                         cudaFuncAttributeMaxDynamicSharedMemorySize, DSMEM);
    cudaFuncSetAttribute(scan3_kernel,
                         cudaFuncAttributeMaxDynamicSharedMemorySize,
                         SC3_SMEM);

    // 1. softplus(ln1(x)) + all weight converts/splits
    ln1_mega_kernel<<<LN1_GRID, 256>>>(x, ln1_w, W_dbc, W_fc, W_proj, W_dt,
                                       h0, h0h, h0l, wdbh, wdbl, wfcf, wprf,
                                       wdth, wdtl);

    // 2. dbc partials: split-K x4 (M=4096, N=96, K=1024) [bf16 3-term WMMA]
    gemm_dbc2_kernel<<<dim3(ML_ / 128, 4), 256, S2TOT>>>(h0h, h0l, wdbh, wdbl,
                                                         dbcp);

    // 3. dbc = sum of partials (+ dlr bf16 hi/lo emit)
    dbcred_kernel<<<ML_ * E_ / 1024, 256>>>(dbcp, dbc, dlrh, dlrl);

    // 4. delta = softplus(dlr @ W_dt^T + b_dt)  [bf16 3-term HMMA]
    gemm_delta_kernel<<<dim3(D_ / 128, ML_ / 128), 256, DSMEM>>>(
        dlrh, dlrl, wdth, wdtl, b_dt, delta);

    // 5. h = h0 + ssm(h0)   [chunked block-parallel scan]
    scan3_kernel<<<dim3(D_ / 32, B_), 512, SC3_SMEM>>>(h0, delta, dbc, A_log,
                                                       Dp, h);

    // 6. m0 = ln2(h) -> fp16
    ln2_kernel<<<ML_, 256>>>(h, ln2_w, m0f);

    // 7. fc = gelu(m0 @ W_fc^T) -> fp16   (M=4096, N=4096, K=1024)
    gemm_hmma_kernel<1><<<dim3(F_ / 128, ML_ / 128), 256, HSMEM_TOTAL>>>(
        m0f, wfcf, D_, fcf, nullptr, nullptr, F_);

    // 8. out = h + fc @ W_proj^T   (M=4096, N=1024, K=4096)
    gemm_hmma_kernel<2><<<dim3(D_ / 128, ML_ / 128), 256, HSMEM_TOTAL>>>(
        fcf, wprf, F_, nullptr, out, h, D_);
}

// round 16
// speedup vs baseline: 1.1976x; 1.0895x over previous
#include <cuda_runtime.h>
#include <cuda_bf16.h>
#include <cuda_fp16.h>
#include <mma.h>
#include <math.h>
#include <stdint.h>

using namespace nvcuda;

// Shapes (fixed by the problem)
#define B_ 4
#define L_ 1024
#define D_ 1024
#define NS_ 16
#define R_ 64
#define E_ 96          // R + 2N
#define F_ 4096        // 4*D
#define ML_ (B_ * L_)  // 4096

// ---------------------------------------------------------------------------
// Scratch (no allocations allowed -> __device__ globals)
// ---------------------------------------------------------------------------
__device__ float g_h0[(size_t)ML_ * D_];       // softplus(ln1(x))
__device__ float g_dbc[(size_t)ML_ * E_];      // h0 @ W_dbc^T
__device__ float g_dbcp[4][(size_t)ML_ * E_];  // split-K partials
__device__ float g_delta[(size_t)ML_ * D_];    // softplus(dlr @ W_dt^T + b_dt)
__device__ float g_h[(size_t)ML_ * D_];        // h0 + ssm(h0)

// bf16 hi/lo splits (precision-sensitive tensor paths)
__device__ __nv_bfloat16 g_h0h[(size_t)ML_ * D_];
__device__ __nv_bfloat16 g_h0l[(size_t)ML_ * D_];
__device__ __nv_bfloat16 g_wdbh[(size_t)E_ * D_];
__device__ __nv_bfloat16 g_wdbl[(size_t)E_ * D_];
__device__ __nv_bfloat16 g_dlrh[(size_t)ML_ * R_];
__device__ __nv_bfloat16 g_dlrl[(size_t)ML_ * R_];
__device__ __nv_bfloat16 g_wdth[(size_t)D_ * R_];
__device__ __nv_bfloat16 g_wdtl[(size_t)D_ * R_];

// fp16 single operands for the two big GEMMs
__device__ __half g_m0f[(size_t)ML_ * D_];
__device__ __half g_fcf[(size_t)ML_ * F_];
__device__ __half g_wfcf[(size_t)F_ * D_];
__device__ __half g_wprf[(size_t)D_ * F_];

// ---------------------------------------------------------------------------
// Activations
// ---------------------------------------------------------------------------
__device__ __forceinline__ float softplus_f(float v) {
    return fmaxf(v, 0.0f) + log1pf(__expf(-fabsf(v)));
}
__device__ __forceinline__ float gelu_f(float v) {
    const float c = 0.7978845608028654f;
    float v3 = v * v * v;
    return 0.5f * v * (1.0f + tanhf(c * (v + 0.044715f * v3)));
}

// ---------------------------------------------------------------------------
// PTX helpers
// ---------------------------------------------------------------------------
__device__ __forceinline__ uint32_t smem_u32(const void* p) {
    uint32_t a;
    asm("{ .reg .u64 t; cvta.to.shared.u64 t, %1; cvt.u32.u64 %0, t; }"
        : "=r"(a) : "l"(p));
    return a;
}
__device__ __forceinline__ void cp_async8(uint32_t dst, const void* src) {
    asm volatile("cp.async.ca.shared.global [%0], [%1], 8;\n"
                 :: "r"(dst), "l"(src));
}
__device__ __forceinline__ void cp_commit() {
    asm volatile("cp.async.commit_group;\n" ::: "memory");
}
template <int N>
__device__ __forceinline__ void cp_wait() {
    asm volatile("cp.async.wait_group %0;\n" :: "n"(N) : "memory");
}

// ---------------------------------------------------------------------------
// Big HMMA fp16 GEMM: CTA 128x128, BK=64, 8 warps (4x2), warp tile 32x64,
// double-buffered cp.async. __launch_bounds__(256,2) -> 2 CTAs/SM
// (4 warps/SMSP) to hide fragment-load->mma latency.
// Inner loop restructured (fb loaded one at a time) to keep live fragments
// at 88 regs so the 128-reg cap does not spill.
// EPI==1: C = gelu(acc) -> fp16 Ch.   EPI==2: C = acc + addv -> fp32 Cf.
// ---------------------------------------------------------------------------
#define HPAD 72                      // halves per row (64 + 8); 144B stride
#define HTILE_B (128 * HPAD * 2)     // 18432 bytes
#define HSTG_B (2 * HTILE_B)         // 36864 bytes per stage (A + B)
#define HSMEM_TOTAL (2 * HSTG_B)     // 73728 bytes (>= 64KB epilogue staging)

template <int EPI>
__global__ __launch_bounds__(256, 2) void gemm_hmma_kernel(
    const __half* __restrict__ A, const __half* __restrict__ Bm, int K,
    __half* __restrict__ Ch, float* __restrict__ Cf,
    const float* __restrict__ addv, int ldc) {
    extern __shared__ char dsm[];
    int tid = threadIdx.x;
    int wid = tid >> 5;
    int wm = wid >> 1;
    int wn = wid & 1;
    int bm = blockIdx.y * 128;
    int bn = blockIdx.x * 128;

    wmma::fragment<wmma::accumulator, 16, 16, 16, float> acc[2][4];
#pragma unroll
    for (int i = 0; i < 2; i++)
#pragma unroll
        for (int j = 0; j < 4; j++) wmma::fill_fragment(acc[i][j], 0.0f);

    auto load_chunk = [&](int st, int kc) {
        uint32_t sb = smem_u32(dsm) + st * HSTG_B;
        int k0 = kc * 64;
#pragma unroll
        for (int j = 0; j < 8; j++) {
            int idx = tid + j * 256;   // 0..2047
            int r = idx >> 4;          // 0..127
            int g = idx & 15;          // 16 groups of 4 halves
            uint32_t so = (uint32_t)(r * (HPAD * 2) + g * 8);
            cp_async8(sb + so, A + (size_t)(bm + r) * K + k0 + g * 4);
            cp_async8(sb + HTILE_B + so,
                      Bm + (size_t)(bn + r) * K + k0 + g * 4);
        }
    };

    const int NC = K / 64;
    load_chunk(0, 0);
    cp_commit();

    for (int kc = 0; kc < NC; kc++) {
        int st = kc & 1;
        if (kc + 1 < NC) {
            load_chunk(st ^ 1, kc + 1);
            cp_commit();
            cp_wait<1>();
        } else {
            cp_wait<0>();
        }
        __syncthreads();

        const __half* sA = (const __half*)(dsm + st * HSTG_B);
        const __half* sB = (const __half*)(dsm + st * HSTG_B + HTILE_B);

#pragma unroll
        for (int kk = 0; kk < 64; kk += 16) {
            wmma::fragment<wmma::matrix_a, 16, 16, 16, __half,
                           wmma::row_major> fa[2];
#pragma unroll
            for (int i = 0; i < 2; i++)
                wmma::load_matrix_sync(fa[i],
                                       sA + (wm * 32 + i * 16) * HPAD + kk,
                                       HPAD);
#pragma unroll
            for (int j = 0; j < 4; j++) {
                wmma::fragment<wmma::matrix_b, 16, 16, 16, __half,
                               wmma::col_major> fb;
                wmma::load_matrix_sync(fb,
                                       sB + (wn * 64 + j * 16) * HPAD + kk,
                                       HPAD);
#pragma unroll
                for (int i = 0; i < 2; i++)
                    wmma::mma_sync(acc[i][j], fa[i], fb, acc[i][j]);
            }
        }
        __syncthreads();
    }

    // Epilogue via smem fp32 staging tile for coalesced writes
    float* sC = (float*)dsm;
#pragma unroll
    for (int i = 0; i < 2; i++)
#pragma unroll
        for (int j = 0; j < 4; j++)
            wmma::store_matrix_sync(sC + (wm * 32 + i * 16) * 128 +
                                        (wn * 64 + j * 16),
                                    acc[i][j], 128, wmma::mem_row_major);
    __syncthreads();

#pragma unroll
    for (int it = 0; it < 16; it++) {
        int idx = tid + it * 256;
        int r = idx >> 5;
        int c4 = idx & 31;
        float4 v = ((const float4*)(sC + r * 128))[c4];
        size_t row = bm + r;
        size_t col = bn + c4 * 4;
        if (EPI == 1) {
            __half o[4];
            o[0] = __float2half(gelu_f(v.x));
            o[1] = __float2half(gelu_f(v.y));
            o[2] = __float2half(gelu_f(v.z));
            o[3] = __float2half(gelu_f(v.w));
            *(uint2*)(Ch + row * ldc + col) = *(uint2*)o;
        } else {
            const float4 av = *(const float4*)(addv + row * ldc + col);
            *(float4*)(Cf + row * ldc + col) =
                make_float4(v.x + av.x, v.y + av.y, v.z + av.z, v.w + av.w);
        }
    }
}

// ---------------------------------------------------------------------------
// dbc split-K: C_partial[kz][4096,96] = Ah/Al[:,kz*256:+256] @ B^T slice.
// Grid (32, 4). bf16 3-term compensation.
// ---------------------------------------------------------------------------
#define S2PAD 36
#define S2A (128 * S2PAD * 2)
#define S2B (96 * S2PAD * 2)
#define S2STG (2 * S2A + 2 * S2B)
#define S2TOT (2 * S2STG)

__global__ __launch_bounds__(256) void gemm_dbc2_kernel(
    const __nv_bfloat16* __restrict__ Ah, const __nv_bfloat16* __restrict__ Al,
    const __nv_bfloat16* __restrict__ Bh, const __nv_bfloat16* __restrict__ Bl,
    float* __restrict__ P) {
    extern __shared__ char dsm[];
    int tid = threadIdx.x;
    int wid = tid >> 5;
    int bm = blockIdx.x * 128;
    int kz = blockIdx.y;
    const int K = D_;
    const int k0base = kz * 256;
    float* C = P + (size_t)kz * ML_ * E_;

    wmma::fragment<wmma::accumulator, 16, 16, 16, float> acc[6];
#pragma unroll
    for (int j = 0; j < 6; j++) wmma::fill_fragment(acc[j], 0.0f);

    auto load_chunk = [&](int st, int kc) {
        uint32_t sb = smem_u32(dsm) + st * S2STG;
        int k0 = k0base + kc * 32;
#pragma unroll
        for (int j = 0; j < 4; j++) {
            int idx = tid + j * 256;
            int r = idx >> 3, cg = idx & 7;
            uint32_t so = (uint32_t)(r * (S2PAD * 2) + cg * 8);
            size_t ao = (size_t)(bm + r) * K + k0 + cg * 4;
            cp_async8(sb + so, Ah + ao);
            cp_async8(sb + S2A + so, Al + ao);
        }
#pragma unroll
        for (int j = 0; j < 3; j++) {
            int idx = tid + j * 256;
            int r = idx >> 3, cg = idx & 7;
            uint32_t so = (uint32_t)(r * (S2PAD * 2) + cg * 8);
            size_t bo = (size_t)r * K + k0 + cg * 4;
            cp_async8(sb + 2 * S2A + so, Bh + bo);
            cp_async8(sb + 2 * S2A + S2B + so, Bl + bo);
        }
    };

    const int NC = 8;
    load_chunk(0, 0);
    cp_commit();

    for (int kc = 0; kc < NC; kc++) {
        int st = kc & 1;
        if (kc + 1 < NC) {
            load_chunk(st ^ 1, kc + 1);
            cp_commit();
            cp_wait<1>();
        } else {
            cp_wait<0>();
        }
        __syncthreads();

        const __nv_bfloat16* sAh = (const __nv_bfloat16*)(dsm + st * S2STG);
        const __nv_bfloat16* sAl =
            (const __nv_bfloat16*)(dsm + st * S2STG + S2A);
        const __nv_bfloat16* sBh =
            (const __nv_bfloat16*)(dsm + st * S2STG + 2 * S2A);
        const __nv_bfloat16* sBl =
            (const __nv_bfloat16*)(dsm + st * S2STG + 2 * S2A + S2B);

#pragma unroll
        for (int kk = 0; kk < 32; kk += 16) {
            wmma::fragment<wmma::matrix_a, 16, 16, 16, __nv_bfloat16,
                           wmma::row_major> fah, fal;
            wmma::fragment<wmma::matrix_b, 16, 16, 16, __nv_bfloat16,
                           wmma::col_major> fbh[6], fbl[6];
            int r0 = wid * 16;
            wmma::load_matrix_sync(fah, sAh + r0 * S2PAD + kk, S2PAD);
            wmma::load_matrix_sync(fal, sAl + r0 * S2PAD + kk, S2PAD);
#pragma unroll
            for (int j = 0; j < 6; j++) {
                wmma::load_matrix_sync(fbh[j], sBh + j * 16 * S2PAD + kk,
                                       S2PAD);
                wmma::load_matrix_sync(fbl[j], sBl + j * 16 * S2PAD + kk,
                                       S2PAD);
            }
#pragma unroll
            for (int j = 0; j < 6; j++) {
                wmma::mma_sync(acc[j], fah, fbh[j], acc[j]);
                wmma::mma_sync(acc[j], fal, fbh[j], acc[j]);
                wmma::mma_sync(acc[j], fah, fbl[j], acc[j]);
            }
        }
        __syncthreads();
    }

    float* sC = (float*)dsm;
#pragma unroll
    for (int j = 0; j < 6; j++)
        wmma::store_matrix_sync(sC + (wid * 16) * 96 + j * 16, acc[j], 96,
                                wmma::mem_row_major);
    __syncthreads();

#pragma unroll
    for (int it = 0; it < 12; it++) {
        int idx = tid + it * 256;
        int r = idx / 24;
        int c4 = idx % 24;
        float4 v = ((const float4*)sC)[idx];
        *(float4*)(C + (size_t)(bm + r) * E_ + c4 * 4) = v;
    }
}

// Deterministic fixed-order reduce of 4 split-K partials.
// Also emits dlr (= dbc[:, 0:64]) as bf16 hi/lo for the delta HMMA GEMM.
__global__ __launch_bounds__(256) void dbcred_kernel(
    const float* __restrict__ P, float* __restrict__ C,
    __nv_bfloat16* __restrict__ dlrh, __nv_bfloat16* __restrict__ dlrl) {
    int i = blockIdx.x * 256 + threadIdx.x;  // float4 index < 98304
    const size_t stride = (size_t)ML_ * E_ / 4;
    const float4* p = (const float4*)P;
    float4 a = p[i];
    float4 b = p[stride + i];
    float4 c = p[2 * stride + i];
    float4 d = p[3 * stride + i];
    float4 o = make_float4(((a.x + b.x) + (c.x + d.x)),
                           ((a.y + b.y) + (c.y + d.y)),
                           ((a.z + b.z) + (c.z + d.z)),
                           ((a.w + b.w) + (c.w + d.w)));
    ((float4*)C)[i] = o;
    int r = i / 24;
    int c4 = i % 24;
    if (c4 < 16) {  // cols < 64 -> dlr path
        float vv[4] = {o.x, o.y, o.z, o.w};
        __nv_bfloat16 h[4], l[4];
#pragma unroll
        for (int j = 0; j < 4; j++) {
            h[j] = __float2bfloat16(vv[j]);
            l[j] = __float2bfloat16(vv[j] - __bfloat162float(h[j]));
        }
        ((uint2*)dlrh)[r * 16 + c4] = *(uint2*)h;
        ((uint2*)dlrl)[r * 16 + c4] = *(uint2*)l;
    }
}

// ---------------------------------------------------------------------------
// delta HMMA GEMM: delta[4096,1024] = softplus(dlr @ W_dt^T + b_dt)
// bf16 3-term, K=64 single-shot. CTA 128x128, 8 warps (4x2).
// ---------------------------------------------------------------------------
#define DT_TILE (128 * HPAD * 2)   // 18432 bytes (K=64 + pad rows)
#define DSMEM (4 * DT_TILE)        // 73728 bytes (>= 64KB epilogue staging)

__global__ __launch_bounds__(256) void gemm_delta_kernel(
    const __nv_bfloat16* __restrict__ Ah, const __nv_bfloat16* __restrict__ Al,
    const __nv_bfloat16* __restrict__ Bh, const __nv_bfloat16* __restrict__ Bl,
    const float* __restrict__ bias, float* __restrict__ C) {
    extern __shared__ char dsm[];
    int tid = threadIdx.x;
    int wid = tid >> 5;
    int wm = wid >> 1;
    int wn = wid & 1;
    int bm = blockIdx.y * 128;
    int bn = blockIdx.x * 128;

    // Load all four 128x64 bf16 tiles (Ah, Al, Bh, Bl)
    {
        uint32_t sb = smem_u32(dsm);
#pragma unroll
        for (int j = 0; j < 8; j++) {
            int idx = tid + j * 256;   // 0..2047
            int r = idx >> 4;          // 0..127
            int g = idx & 15;          // groups of 4 halves
            uint32_t so = (uint32_t)(r * (HPAD * 2) + g * 8);
            size_t ao = (size_t)(bm + r) * R_ + g * 4;
            size_t bo = (size_t)(bn + r) * R_ + g * 4;
            cp_async8(sb + so, Ah + ao);
            cp_async8(sb + DT_TILE + so, Al + ao);
            cp_async8(sb + 2 * DT_TILE + so, Bh + bo);
            cp_async8(sb + 3 * DT_TILE + so, Bl + bo);
        }
        cp_commit();
        cp_wait<0>();
        __syncthreads();
    }

    const __nv_bfloat16* sAh = (const __nv_bfloat16*)dsm;
    const __nv_bfloat16* sAl = (const __nv_bfloat16*)(dsm + DT_TILE);
    const __nv_bfloat16* sBh = (const __nv_bfloat16*)(dsm + 2 * DT_TILE);
    const __nv_bfloat16* sBl = (const __nv_bfloat16*)(dsm + 3 * DT_TILE);

    wmma::fragment<wmma::accumulator, 16, 16, 16, float> acc[2][4];
#pragma unroll
    for (int i = 0; i < 2; i++)
#pragma unroll
        for (int j = 0; j < 4; j++) wmma::fill_fragment(acc[i][j], 0.0f);

#pragma unroll
    for (int kk = 0; kk < 64; kk += 16) {
        wmma::fragment<wmma::matrix_a, 16, 16, 16, __nv_bfloat16,
                       wmma::row_major> fah[2], fal[2];
        wmma::fragment<wmma::matrix_b, 16, 16, 16, __nv_bfloat16,
                       wmma::col_major> fbh[4], fbl[4];
#pragma unroll
        for (int i = 0; i < 2; i++) {
            int r0 = wm * 32 + i * 16;
            wmma::load_matrix_sync(fah[i], sAh + r0 * HPAD + kk, HPAD);
            wmma::load_matrix_sync(fal[i], sAl + r0 * HPAD + kk, HPAD);
        }
#pragma unroll
        for (int j = 0; j < 4; j++) {
            int c0 = wn * 64 + j * 16;
            wmma::load_matrix_sync(fbh[j], sBh + c0 * HPAD + kk, HPAD);
            wmma::load_matrix_sync(fbl[j], sBl + c0 * HPAD + kk, HPAD);
        }
#pragma unroll
        for (int i = 0; i < 2; i++)
#pragma unroll
            for (int j = 0; j < 4; j++) {
                wmma::mma_sync(acc[i][j], fah[i], fbh[j], acc[i][j]);
                wmma::mma_sync(acc[i][j], fal[i], fbh[j], acc[i][j]);
                wmma::mma_sync(acc[i][j], fah[i], fbl[j], acc[i][j]);
            }
    }
    __syncthreads();

    float* sC = (float*)dsm;
#pragma unroll
    for (int i = 0; i < 2; i++)
#pragma unroll
        for (int j = 0; j < 4; j++)
            wmma::store_matrix_sync(sC + (wm * 32 + i * 16) * 128 +
                                        (wn * 64 + j * 16),
                                    acc[i][j], 128, wmma::mem_row_major);
    __syncthreads();

#pragma unroll
    for (int it = 0; it < 16; it++) {
        int idx = tid + it * 256;
        int r = idx >> 5;
        int c4 = idx & 31;
        float4 v = ((const float4*)(sC + r * 128))[c4];
        size_t row = bm + r;
        size_t col = bn + c4 * 4;
        const float4 bv = *(const float4*)(bias + col);
        float4 o = make_float4(softplus_f(v.x + bv.x), softplus_f(v.y + bv.y),
                               softplus_f(v.z + bv.z), softplus_f(v.w + bv.w));
        *(float4*)(C + row * D_ + col) = o;
    }
}

// ---------------------------------------------------------------------------
// ln1 mega-fused. Block ranges:
//  [0, ML_)                      : softplus(ln(x)) -> fp32 + bf16 hi/lo
//  [ML_, +96)                    : W_dbc -> bf16 hi/lo
//  [ML_+96, +4096)               : W_fc -> fp16
//  [ML_+4192, +4096)             : W_proj -> fp16
//  [ML_+8288, +64)               : W_dt -> bf16 hi/lo
// ---------------------------------------------------------------------------
#define LN1_GRID (ML_ + 96 + 4096 + 4096 + 64)

__global__ __launch_bounds__(256) void ln1_mega_kernel(
    const float* __restrict__ x, const float* __restrict__ w,
    const float* __restrict__ W_dbc, const float* __restrict__ W_fc,
    const float* __restrict__ W_proj, const float* __restrict__ W_dt,
    float* __restrict__ out, __nv_bfloat16* __restrict__ oh,
    __nv_bfloat16* __restrict__ ol,
    __nv_bfloat16* __restrict__ wdh, __nv_bfloat16* __restrict__ wdl,
    __half* __restrict__ wfcf, __half* __restrict__ wprf,
    __nv_bfloat16* __restrict__ wdth, __nv_bfloat16* __restrict__ wdtl) {
    __shared__ float red[8];
    int bid = blockIdx.x;
    int t = threadIdx.x;

    if (bid >= ML_) {
        int r = bid - ML_;
        if (r < 96) {  // W_dbc bf16 hi/lo split
            int i = r * 256 + t;
            float4 v = ((const float4*)W_dbc)[i];
            float vv[4] = {v.x, v.y, v.z, v.w};
            __nv_bfloat16 h[4], l[4];
#pragma unroll
            for (int j = 0; j < 4; j++) {
                h[j] = __float2bfloat16(vv[j]);
                l[j] = __float2bfloat16(vv[j] - __bfloat162float(h[j]));
            }
            ((uint2*)wdh)[i] = *(uint2*)h;
            ((uint2*)wdl)[i] = *(uint2*)l;
        } else if (r < 96 + 4096) {  // W_fc -> fp16
            int i = (r - 96) * 256 + t;
            float4 v = ((const float4*)W_fc)[i];
            __half h[4] = {__float2half(v.x), __float2half(v.y),
                           __float2half(v.z), __float2half(v.w)};
            ((uint2*)wfcf)[i] = *(uint2*)h;
        } else if (r < 96 + 8192) {  // W_proj -> fp16
            int i = (r - 96 - 4096) * 256 + t;
            float4 v = ((const float4*)W_proj)[i];
            __half h[4] = {__float2half(v.x), __float2half(v.y),
                           __float2half(v.z), __float2half(v.w)};
            ((uint2*)wprf)[i] = *(uint2*)h;
        } else {  // W_dt bf16 hi/lo split (16384 float4)
            int i = (r - 96 - 8192) * 256 + t;
            float4 v = ((const float4*)W_dt)[i];
            float vv[4] = {v.x, v.y, v.z, v.w};
            __nv_bfloat16 h[4], l[4];
#pragma unroll
            for (int j = 0; j < 4; j++) {
                h[j] = __float2bfloat16(vv[j]);
                l[j] = __float2bfloat16(vv[j] - __bfloat162float(h[j]));
            }
            ((uint2*)wdth)[i] = *(uint2*)h;
            ((uint2*)wdtl)[i] = *(uint2*)l;
        }
        return;
    }

    int row = bid;
    const float4* xr = (const float4*)(x + (size_t)row * D_);
    float4 v = xr[t];

    float s = v.x + v.y + v.z + v.w;
#pragma unroll
    for (int m = 16; m > 0; m >>= 1) s += __shfl_xor_sync(0xffffffffu, s, m);
    if ((t & 31) == 0) red[t >> 5] = s;
    __syncthreads();
    float tot = 0.0f;
#pragma unroll
    for (int i = 0; i < 8; i++) tot += red[i];
    float mu = tot * (1.0f / D_);

    float cx = v.x - mu, cy = v.y - mu, cz = v.z - mu, cw = v.w - mu;
    float s2 = cx * cx + cy * cy + cz * cz + cw * cw;
#pragma unroll
    for (int m = 16; m > 0; m >>= 1) s2 += __shfl_xor_sync(0xffffffffu, s2, m);
    __syncthreads();
    if ((t & 31) == 0) red[t >> 5] = s2;
    __syncthreads();
    float tot2 = 0.0f;
#pragma unroll
    for (int i = 0; i < 8; i++) tot2 += red[i];
    float rs = rsqrtf(tot2 * (1.0f / D_) + 1e-5f);

    float4 wv = ((const float4*)w)[t];
    float o[4];
    o[0] = softplus_f(cx * rs * wv.x);
    o[1] = softplus_f(cy * rs * wv.y);
    o[2] = softplus_f(cz * rs * wv.z);
    o[3] = softplus_f(cw * rs * wv.w);
    ((float4*)(out + (size_t)row * D_))[t] = make_float4(o[0], o[1], o[2], o[3]);

    __nv_bfloat16 h[4], l[4];
#pragma unroll
    for (int j = 0; j < 4; j++) {
        h[j] = __float2bfloat16(o[j]);
        l[j] = __float2bfloat16(o[j] - __bfloat162float(h[j]));
    }
    ((uint2*)(oh + (size_t)row * D_))[t] = *(uint2*)h;
    ((uint2*)(ol + (size_t)row * D_))[t] = *(uint2*)l;
}

// ---------------------------------------------------------------------------
// ln2: ln(h) -> fp16 single
// ---------------------------------------------------------------------------
__global__ __launch_bounds__(256) void ln2_kernel(const float* __restrict__ x,
                                                  const float* __restrict__ w,
                                                  __half* __restrict__ o16) {
    int row = blockIdx.x;
    int t = threadIdx.x;
    __shared__ float red[8];

    const float4* xr = (const float4*)(x + (size_t)row * D_);
    float4 v = xr[t];

    float s = v.x + v.y + v.z + v.w;
#pragma unroll
    for (int m = 16; m > 0; m >>= 1) s += __shfl_xor_sync(0xffffffffu, s, m);
    if ((t & 31) == 0) red[t >> 5] = s;
    __syncthreads();
    float tot = 0.0f;
#pragma unroll
    for (int i = 0; i < 8; i++) tot += red[i];
    float mu = tot * (1.0f / D_);

    float cx = v.x - mu, cy = v.y - mu, cz = v.z - mu, cw = v.w - mu;
    float s2 = cx * cx + cy * cy + cz * cz + cw * cw;
#pragma unroll
    for (int m = 16; m > 0; m >>= 1) s2 += __shfl_xor_sync(0xffffffffu, s2, m);
    __syncthreads();
    if ((t & 31) == 0) red[t >> 5] = s2;
    __syncthreads();
    float tot2 = 0.0f;
#pragma unroll
    for (int i = 0; i < 8; i++) tot2 += red[i];
    float rs = rsqrtf(tot2 * (1.0f / D_) + 1e-5f);

    float4 wv = ((const float4*)w)[t];
    __half h[4];
    h[0] = __float2half(cx * rs * wv.x);
    h[1] = __float2half(cy * rs * wv.y);
    h[2] = __float2half(cz * rs * wv.z);
    h[3] = __float2half(cw * rs * wv.w);
    ((uint2*)(o16 + (size_t)row * D_))[t] = *(uint2*)h;
}

// ---------------------------------------------------------------------------
// Selective scan v3.1: block-local chunked parallel scan (unchanged)
// ---------------------------------------------------------------------------
#define NCH 16
#define CHL 64
#define SUBL 32

#define SC3_BC 0
#define SC3_PA 65536
#define SC3_ST 98304
#define SC3_SMEM 131072

__global__ __launch_bounds__(512) void scan3_kernel(
    const float* __restrict__ h0, const float* __restrict__ delta,
    const float* __restrict__ dbc, const float* __restrict__ A_log,
    const float* __restrict__ Dp, float* __restrict__ hout) {
    extern __shared__ char dsm[];
    float* sBC = (float*)(dsm + SC3_BC);
    float* sPA = (float*)(dsm + SC3_PA);
    float* sST = (float*)(dsm + SC3_ST);

    int tid = threadIdx.x;
    int lane = tid & 31;
    int w = tid >> 5;
    int d = blockIdx.x * 32 + lane;
    int b = blockIdx.y;

    float negA0 = -__expf(A_log[d * NS_]);
    float eps[16];
#pragma unroll
    for (int n = 0; n < 16; n++)
        eps[n] = -__expf(A_log[d * NS_ + n]) - (float)(n + 1) * negA0;
    float dp = Dp[d];

    size_t xbase = ((size_t)b * L_ + (size_t)w * CHL) * D_ + d;
    size_t ebase = ((size_t)b * L_ + (size_t)w * CHL) * E_ + R_ + lane;

    float st[16];
#pragma unroll
    for (int n = 0; n < 16; n++) st[n] = 0.0f;
    float sdelta = 0.0f;

    // Phase A: local scan from zero state + sum of deltas
    {
        float pdl[4], pxv[4];
#pragma unroll
        for (int i = 0; i < 4; i++) {
            pdl[i] = delta[xbase + (size_t)i * D_];
            pxv[i] = h0[xbase + (size_t)i * D_];
        }
#pragma unroll
        for (int sub = 0; sub < CHL / SUBL; sub++) {
            float* bcw = sBC + (w * SUBL) * 32;
#pragma unroll 8
            for (int l = 0; l < SUBL; l++)
                bcw[l * 32 + lane] =
                    dbc[ebase + (size_t)(sub * SUBL + l) * E_];
            __syncwarp();

#pragma unroll 4
            for (int l = 0; l < SUBL; l++) {
                int gl = sub * SUBL + l;
                float dv = pdl[gl & 3];
                float xv = pxv[gl & 3];
                int lf = gl + 4;
                if (lf < CHL) {
                    pdl[gl & 3] = delta[xbase + (size_t)lf * D_];
                    pxv[gl & 3] = h0[xbase + (size_t)lf * D_];
                }

                float Bv[16];
                *(float4*)&Bv[0]  = *(const float4*)&bcw[l * 32 + 0];
                *(float4*)&Bv[4]  = *(const float4*)&bcw[l * 32 + 4];
                *(float4*)&Bv[8]  = *(const float4*)&bcw[l * 32 + 8];
                *(float4*)&Bv[12] = *(const float4*)&bcw[l * 32 + 12];

                float p = __expf(dv * negA0);
                float p2 = p * p, p4 = p2 * p2, p8 = p4 * p4;
                float pw[16];
                pw[0] = p;          pw[1] = p2;         pw[2] = p2 * p;
                pw[3] = p4;         pw[4] = p4 * p;     pw[5] = p4 * p2;
                pw[6] = p4 * pw[2]; pw[7] = p8;
                pw[8] = p8 * p;     pw[9] = p8 * p2;    pw[10] = p8 * pw[2];
                pw[11] = p8 * p4;   pw[12] = p8 * pw[4]; pw[13] = p8 * pw[5];
                pw[14] = p8 * pw[6]; pw[15] = p8 * p8;

                sdelta += dv;
                float dx = dv * xv;
#pragma unroll
                for (int n = 0; n < 16; n++) {
                    float a = pw[n] * fmaf(dv, eps[n], 1.0f);
                    st[n] = fmaf(a, st[n], dx * Bv[n]);
                }
            }
            __syncwarp();
        }
    }

    // publish chunk summaries
#pragma unroll
    for (int n = 0; n < 16; n++) {
        float negAn = fmaf((float)(n + 1), negA0, eps[n]);
        sPA[(w * NS_ + n) * 32 + lane] = __expf(negAn * sdelta);
        sST[(w * NS_ + n) * 32 + lane] = st[n];
    }
    __syncthreads();

    // Phase B: block combine
    {
        int cd = tid & 31;
        int cn = tid >> 5;
        float hacc = 0.0f;
#pragma unroll
        for (int wc = 0; wc < NCH; wc++) {
            int off = (wc * NS_ + cn) * 32 + cd;
            float pav = sPA[off];
            float stv = sST[off];
            sPA[off] = hacc;
            hacc = fmaf(pav, hacc, stv);
        }
    }
    __syncthreads();

    // Phase C: re-scan with correct init, emit output
#pragma unroll
    for (int n = 0; n < 16; n++) st[n] = sPA[(w * NS_ + n) * 32 + lane];

    {
        float pdl[4], pxv[4];
#pragma unroll
        for (int i = 0; i < 4; i++) {
            pdl[i] = delta[xbase + (size_t)i * D_];
            pxv[i] = h0[xbase + (size_t)i * D_];
        }
#pragma unroll
        for (int sub = 0; sub < CHL / SUBL; sub++) {
            float* bcw = sBC + (w * SUBL) * 32;
#pragma unroll 8
            for (int l = 0; l < SUBL; l++)
                bcw[l * 32 + lane] =
                    dbc[ebase + (size_t)(sub * SUBL + l) * E_];
            __syncwarp();

#pragma unroll 4
            for (int l = 0; l < SUBL; l++) {
                int gl = sub * SUBL + l;
                float dv = pdl[gl & 3];
                float xv = pxv[gl & 3];
                int lf = gl + 4;
                if (lf < CHL) {
                    pdl[gl & 3] = delta[xbase + (size_t)lf * D_];
                    pxv[gl & 3] = h0[xbase + (size_t)lf * D_];
                }

                float Bv[16], Cv[16];
                *(float4*)&Bv[0]  = *(const float4*)&bcw[l * 32 + 0];
                *(float4*)&Bv[4]  = *(const float4*)&bcw[l * 32 + 4];
                *(float4*)&Bv[8]  = *(const float4*)&bcw[l * 32 + 8];
                *(float4*)&Bv[12] = *(const float4*)&bcw[l * 32 + 12];
                *(float4*)&Cv[0]  = *(const float4*)&bcw[l * 32 + 16];
                *(float4*)&Cv[4]  = *(const float4*)&bcw[l * 32 + 20];
                *(float4*)&Cv[8]  = *(const float4*)&bcw[l * 32 + 24];
                *(float4*)&Cv[12] = *(const float4*)&bcw[l * 32 + 28];

                float p = __expf(dv * negA0);
                float p2 = p * p, p4 = p2 * p2, p8 = p4 * p4;
                float pw[16];
                pw[0] = p;          pw[1] = p2;         pw[2] = p2 * p;
                pw[3] = p4;         pw[4] = p4 * p;     pw[5] = p4 * p2;
                pw[6] = p4 * pw[2]; pw[7] = p8;
                pw[8] = p8 * p;     pw[9] = p8 * p2;    pw[10] = p8 * pw[2];
                pw[11] = p8 * p4;   pw[12] = p8 * pw[4]; pw[13] = p8 * pw[5];
                pw[14] = p8 * pw[6]; pw[15] = p8 * p8;

                float dx = dv * xv;
                float y0 = 0.f, y1 = 0.f, y2 = 0.f, y3 = 0.f;
#pragma unroll
                for (int n = 0; n < 16; n++) {
                    float a = pw[n] * fmaf(dv, eps[n], 1.0f);
                    st[n] = fmaf(a, st[n], dx * Bv[n]);
                    float yv = st[n] * Cv[n];
                    if ((n & 3) == 0) y0 += yv;
                    else if ((n & 3) == 1) y1 += yv;
                    else if ((n & 3) == 2) y2 += yv;
                    else y3 += yv;
                }
                float y = (y0 + y1) + (y2 + y3);
                hout[xbase + (size_t)gl * D_] = fmaf(xv, dp, xv + y);
            }
            __syncwarp();
        }
    }
}

// ---------------------------------------------------------------------------
// Launch
// ---------------------------------------------------------------------------
extern "C" void kernel_launch(void* const* d_in, const int* in_sizes, int n_in,
                              void* d_out, int out_size) {
    const float* x      = (const float*)d_in[0];
    const float* ln1_w  = (const float*)d_in[1];
    const float* ln2_w  = (const float*)d_in[2];
    const float* W_dbc  = (const float*)d_in[3];
    const float* W_dt   = (const float*)d_in[4];
    const float* b_dt   = (const float*)d_in[5];
    const float* A_log  = (const float*)d_in[6];
    const float* Dp     = (const float*)d_in[7];
    const float* W_fc   = (const float*)d_in[8];
    const float* W_proj = (const float*)d_in[9];
    float* out = (float*)d_out;

    float *h0, *dbc, *dbcp, *delta, *h;
    __nv_bfloat16 *h0h, *h0l, *wdbh, *wdbl, *dlrh, *dlrl, *wdth, *wdtl;
    __half *m0f, *fcf, *wfcf, *wprf;
    cudaGetSymbolAddress((void**)&h0, g_h0);
    cudaGetSymbolAddress((void**)&dbc, g_dbc);
    cudaGetSymbolAddress((void**)&dbcp, g_dbcp);
    cudaGetSymbolAddress((void**)&delta, g_delta);
    cudaGetSymbolAddress((void**)&h, g_h);
    cudaGetSymbolAddress((void**)&h0h, g_h0h);
    cudaGetSymbolAddress((void**)&h0l, g_h0l);
    cudaGetSymbolAddress((void**)&wdbh, g_wdbh);
    cudaGetSymbolAddress((void**)&wdbl, g_wdbl);
    cudaGetSymbolAddress((void**)&dlrh, g_dlrh);
    cudaGetSymbolAddress((void**)&dlrl, g_dlrl);
    cudaGetSymbolAddress((void**)&wdth, g_wdth);
    cudaGetSymbolAddress((void**)&wdtl, g_wdtl);
    cudaGetSymbolAddress((void**)&m0f, g_m0f);
    cudaGetSymbolAddress((void**)&fcf, g_fcf);
    cudaGetSymbolAddress((void**)&wfcf, g_wfcf);
    cudaGetSymbolAddress((void**)&wprf, g_wprf);

    cudaFuncSetAttribute(gemm_hmma_kernel<1>,
                         cudaFuncAttributeMaxDynamicSharedMemorySize,
                         HSMEM_TOTAL);
    cudaFuncSetAttribute(gemm_hmma_kernel<2>,
                         cudaFuncAttributeMaxDynamicSharedMemorySize,
                         HSMEM_TOTAL);
    cudaFuncSetAttribute(gemm_dbc2_kernel,
                         cudaFuncAttributeMaxDynamicSharedMemorySize, S2TOT);
    cudaFuncSetAttribute(gemm_delta_kernel,
                         cudaFuncAttributeMaxDynamicSharedMemorySize, DSMEM);
    cudaFuncSetAttribute(scan3_kernel,
                         cudaFuncAttributeMaxDynamicSharedMemorySize,
                         SC3_SMEM);

    // 1. softplus(ln1(x)) + all weight converts/splits
    ln1_mega_kernel<<<LN1_GRID, 256>>>(x, ln1_w, W_dbc, W_fc, W_proj, W_dt,
                                       h0, h0h, h0l, wdbh, wdbl, wfcf, wprf,
                                       wdth, wdtl);

    // 2. dbc partials: split-K x4 (M=4096, N=96, K=1024) [bf16 3-term WMMA]
    gemm_dbc2_kernel<<<dim3(ML_ / 128, 4), 256, S2TOT>>>(h0h, h0l, wdbh, wdbl,
                                                         dbcp);

    // 3. dbc = sum of partials (+ dlr bf16 hi/lo emit)
    dbcred_kernel<<<ML_ * E_ / 1024, 256>>>(dbcp, dbc, dlrh, dlrl);

    // 4. delta = softplus(dlr @ W_dt^T + b_dt)  [bf16 3-term HMMA]
    gemm_delta_kernel<<<dim3(D_ / 128, ML_ / 128), 256, DSMEM>>>(
        dlrh, dlrl, wdth, wdtl, b_dt, delta);

    // 5. h = h0 + ssm(h0)   [chunked block-parallel scan]
    scan3_kernel<<<dim3(D_ / 32, B_), 512, SC3_SMEM>>>(h0, delta, dbc, A_log,
                                                       Dp, h);

    // 6. m0 = ln2(h) -> fp16
    ln2_kernel<<<ML_, 256>>>(h, ln2_w, m0f);

    // 7. fc = gelu(m0 @ W_fc^T) -> fp16   (M=4096, N=4096, K=1024)
    gemm_hmma_kernel<1><<<dim3(F_ / 128, ML_ / 128), 256, HSMEM_TOTAL>>>(
        m0f, wfcf, D_, fcf, nullptr, nullptr, F_);

    // 8. out = h + fc @ W_proj^T   (M=4096, N=1024, K=4096)
    gemm_hmma_kernel<2><<<dim3(D_ / 128, ML_ / 128), 256, HSMEM_TOTAL>>>(
        fcf, wprf, F_, nullptr, out, h, D_);
}

// round 17
// speedup vs baseline: 1.2095x; 1.0100x over previous
#include <cuda_runtime.h>
#include <cuda_bf16.h>
#include <cuda_fp16.h>
#include <mma.h>
#include <math.h>
#include <stdint.h>

using namespace nvcuda;

// Shapes (fixed by the problem)
#define B_ 4
#define L_ 1024
#define D_ 1024
#define NS_ 16
#define R_ 64
#define E_ 96          // R + 2N
#define F_ 4096        // 4*D
#define ML_ (B_ * L_)  // 4096

// ---------------------------------------------------------------------------
// Scratch (no allocations allowed -> __device__ globals)
// ---------------------------------------------------------------------------
__device__ float g_h0[(size_t)ML_ * D_];       // softplus(ln1(x))
__device__ float g_dbc[(size_t)ML_ * E_];      // h0 @ W_dbc^T
__device__ float g_dbcp[4][(size_t)ML_ * E_];  // split-K partials
__device__ float g_delta[(size_t)ML_ * D_];    // softplus(dlr @ W_dt^T + b_dt)
__device__ float g_h[(size_t)ML_ * D_];        // h0 + ssm(h0)

// bf16 hi/lo splits (precision-sensitive tensor paths)
__device__ __nv_bfloat16 g_h0h[(size_t)ML_ * D_];
__device__ __nv_bfloat16 g_h0l[(size_t)ML_ * D_];
__device__ __nv_bfloat16 g_wdbh[(size_t)E_ * D_];
__device__ __nv_bfloat16 g_wdbl[(size_t)E_ * D_];
__device__ __nv_bfloat16 g_dlrh[(size_t)ML_ * R_];
__device__ __nv_bfloat16 g_dlrl[(size_t)ML_ * R_];
__device__ __nv_bfloat16 g_wdth[(size_t)D_ * R_];
__device__ __nv_bfloat16 g_wdtl[(size_t)D_ * R_];

// fp16 single operands for the two big GEMMs
__device__ __half g_m0f[(size_t)ML_ * D_];
__device__ __half g_fcf[(size_t)ML_ * F_];
__device__ __half g_wfcf[(size_t)F_ * D_];
__device__ __half g_wprf[(size_t)D_ * F_];

// ---------------------------------------------------------------------------
// Activations
// ---------------------------------------------------------------------------
__device__ __forceinline__ float softplus_f(float v) {
    return fmaxf(v, 0.0f) + log1pf(__expf(-fabsf(v)));
}
__device__ __forceinline__ float gelu_f(float v) {
    const float c = 0.7978845608028654f;
    float v3 = v * v * v;
    return 0.5f * v * (1.0f + tanhf(c * (v + 0.044715f * v3)));
}

// ---------------------------------------------------------------------------
// PTX helpers
// ---------------------------------------------------------------------------
__device__ __forceinline__ uint32_t smem_u32(const void* p) {
    uint32_t a;
    asm("{ .reg .u64 t; cvta.to.shared.u64 t, %1; cvt.u32.u64 %0, t; }"
        : "=r"(a) : "l"(p));
    return a;
}
__device__ __forceinline__ void cp_async8(uint32_t dst, const void* src) {
    asm volatile("cp.async.ca.shared.global [%0], [%1], 8;\n"
                 :: "r"(dst), "l"(src));
}
__device__ __forceinline__ void cp_commit() {
    asm volatile("cp.async.commit_group;\n" ::: "memory");
}
template <int N>
__device__ __forceinline__ void cp_wait() {
    asm volatile("cp.async.wait_group %0;\n" :: "n"(N) : "memory");
}

// ---------------------------------------------------------------------------
// Big HMMA fp16 GEMM: CTA 128x128, BK=64, 8 warps (4x2), warp tile 32x64,
// double-buffered cp.async, __launch_bounds__(256,2) (latency-bound fix).
// EPI==1: C = gelu(acc) -> fp16 Ch.   EPI==2: C = acc + addv -> fp32 Cf.
// ---------------------------------------------------------------------------
#define HPAD 72                      // halves per row (64 + 8); 144B stride
#define HTILE_B (128 * HPAD * 2)     // 18432 bytes
#define HSTG_B (2 * HTILE_B)         // 36864 bytes per stage (A + B)
#define HSMEM_TOTAL (2 * HSTG_B)     // 73728 bytes (>= 64KB epilogue staging)

template <int EPI>
__global__ __launch_bounds__(256, 2) void gemm_hmma_kernel(
    const __half* __restrict__ A, const __half* __restrict__ Bm, int K,
    __half* __restrict__ Ch, float* __restrict__ Cf,
    const float* __restrict__ addv, int ldc) {
    extern __shared__ char dsm[];
    int tid = threadIdx.x;
    int wid = tid >> 5;
    int wm = wid >> 1;
    int wn = wid & 1;
    int bm = blockIdx.y * 128;
    int bn = blockIdx.x * 128;

    wmma::fragment<wmma::accumulator, 16, 16, 16, float> acc[2][4];
#pragma unroll
    for (int i = 0; i < 2; i++)
#pragma unroll
        for (int j = 0; j < 4; j++) wmma::fill_fragment(acc[i][j], 0.0f);

    auto load_chunk = [&](int st, int kc) {
        uint32_t sb = smem_u32(dsm) + st * HSTG_B;
        int k0 = kc * 64;
#pragma unroll
        for (int j = 0; j < 8; j++) {
            int idx = tid + j * 256;   // 0..2047
            int r = idx >> 4;          // 0..127
            int g = idx & 15;          // 16 groups of 4 halves
            uint32_t so = (uint32_t)(r * (HPAD * 2) + g * 8);
            cp_async8(sb + so, A + (size_t)(bm + r) * K + k0 + g * 4);
            cp_async8(sb + HTILE_B + so,
                      Bm + (size_t)(bn + r) * K + k0 + g * 4);
        }
    };

    const int NC = K / 64;
    load_chunk(0, 0);
    cp_commit();

    for (int kc = 0; kc < NC; kc++) {
        int st = kc & 1;
        if (kc + 1 < NC) {
            load_chunk(st ^ 1, kc + 1);
            cp_commit();
            cp_wait<1>();
        } else {
            cp_wait<0>();
        }
        __syncthreads();

        const __half* sA = (const __half*)(dsm + st * HSTG_B);
        const __half* sB = (const __half*)(dsm + st * HSTG_B + HTILE_B);

#pragma unroll
        for (int kk = 0; kk < 64; kk += 16) {
            wmma::fragment<wmma::matrix_a, 16, 16, 16, __half,
                           wmma::row_major> fa[2];
#pragma unroll
            for (int i = 0; i < 2; i++)
                wmma::load_matrix_sync(fa[i],
                                       sA + (wm * 32 + i * 16) * HPAD + kk,
                                       HPAD);
#pragma unroll
            for (int j = 0; j < 4; j++) {
                wmma::fragment<wmma::matrix_b, 16, 16, 16, __half,
                               wmma::col_major> fb;
                wmma::load_matrix_sync(fb,
                                       sB + (wn * 64 + j * 16) * HPAD + kk,
                                       HPAD);
#pragma unroll
                for (int i = 0; i < 2; i++)
                    wmma::mma_sync(acc[i][j], fa[i], fb, acc[i][j]);
            }
        }
        __syncthreads();
    }

    // Epilogue via smem fp32 staging tile for coalesced writes
    float* sC = (float*)dsm;
#pragma unroll
    for (int i = 0; i < 2; i++)
#pragma unroll
        for (int j = 0; j < 4; j++)
            wmma::store_matrix_sync(sC + (wm * 32 + i * 16) * 128 +
                                        (wn * 64 + j * 16),
                                    acc[i][j], 128, wmma::mem_row_major);
    __syncthreads();

#pragma unroll
    for (int it = 0; it < 16; it++) {
        int idx = tid + it * 256;
        int r = idx >> 5;
        int c4 = idx & 31;
        float4 v = ((const float4*)(sC + r * 128))[c4];
        size_t row = bm + r;
        size_t col = bn + c4 * 4;
        if (EPI == 1) {
            __half o[4];
            o[0] = __float2half(gelu_f(v.x));
            o[1] = __float2half(gelu_f(v.y));
            o[2] = __float2half(gelu_f(v.z));
            o[3] = __float2half(gelu_f(v.w));
            *(uint2*)(Ch + row * ldc + col) = *(uint2*)o;
        } else {
            const float4 av = *(const float4*)(addv + row * ldc + col);
            *(float4*)(Cf + row * ldc + col) =
                make_float4(v.x + av.x, v.y + av.y, v.z + av.z, v.w + av.w);
        }
    }
}

// ---------------------------------------------------------------------------
// dbc split-K: C_partial[kz][4096,96] = Ah/Al[:,kz*256:+256] @ B^T slice.
// Grid (32, 4). bf16 3-term compensation. __launch_bounds__(256,2):
// inner loop restructured (fb loaded per-j) -> live frags 80 regs.
// ---------------------------------------------------------------------------
#define S2PAD 36
#define S2A (128 * S2PAD * 2)
#define S2B (96 * S2PAD * 2)
#define S2STG (2 * S2A + 2 * S2B)
#define S2TOT (2 * S2STG)

__global__ __launch_bounds__(256, 2) void gemm_dbc2_kernel(
    const __nv_bfloat16* __restrict__ Ah, const __nv_bfloat16* __restrict__ Al,
    const __nv_bfloat16* __restrict__ Bh, const __nv_bfloat16* __restrict__ Bl,
    float* __restrict__ P) {
    extern __shared__ char dsm[];
    int tid = threadIdx.x;
    int wid = tid >> 5;
    int bm = blockIdx.x * 128;
    int kz = blockIdx.y;
    const int K = D_;
    const int k0base = kz * 256;
    float* C = P + (size_t)kz * ML_ * E_;

    wmma::fragment<wmma::accumulator, 16, 16, 16, float> acc[6];
#pragma unroll
    for (int j = 0; j < 6; j++) wmma::fill_fragment(acc[j], 0.0f);

    auto load_chunk = [&](int st, int kc) {
        uint32_t sb = smem_u32(dsm) + st * S2STG;
        int k0 = k0base + kc * 32;
#pragma unroll
        for (int j = 0; j < 4; j++) {
            int idx = tid + j * 256;
            int r = idx >> 3, cg = idx & 7;
            uint32_t so = (uint32_t)(r * (S2PAD * 2) + cg * 8);
            size_t ao = (size_t)(bm + r) * K + k0 + cg * 4;
            cp_async8(sb + so, Ah + ao);
            cp_async8(sb + S2A + so, Al + ao);
        }
#pragma unroll
        for (int j = 0; j < 3; j++) {
            int idx = tid + j * 256;
            int r = idx >> 3, cg = idx & 7;
            uint32_t so = (uint32_t)(r * (S2PAD * 2) + cg * 8);
            size_t bo = (size_t)r * K + k0 + cg * 4;
            cp_async8(sb + 2 * S2A + so, Bh + bo);
            cp_async8(sb + 2 * S2A + S2B + so, Bl + bo);
        }
    };

    const int NC = 8;
    load_chunk(0, 0);
    cp_commit();

    for (int kc = 0; kc < NC; kc++) {
        int st = kc & 1;
        if (kc + 1 < NC) {
            load_chunk(st ^ 1, kc + 1);
            cp_commit();
            cp_wait<1>();
        } else {
            cp_wait<0>();
        }
        __syncthreads();

        const __nv_bfloat16* sAh = (const __nv_bfloat16*)(dsm + st * S2STG);
        const __nv_bfloat16* sAl =
            (const __nv_bfloat16*)(dsm + st * S2STG + S2A);
        const __nv_bfloat16* sBh =
            (const __nv_bfloat16*)(dsm + st * S2STG + 2 * S2A);
        const __nv_bfloat16* sBl =
            (const __nv_bfloat16*)(dsm + st * S2STG + 2 * S2A + S2B);

#pragma unroll
        for (int kk = 0; kk < 32; kk += 16) {
            wmma::fragment<wmma::matrix_a, 16, 16, 16, __nv_bfloat16,
                           wmma::row_major> fah, fal;
            int r0 = wid * 16;
            wmma::load_matrix_sync(fah, sAh + r0 * S2PAD + kk, S2PAD);
            wmma::load_matrix_sync(fal, sAl + r0 * S2PAD + kk, S2PAD);
#pragma unroll
            for (int j = 0; j < 6; j++) {
                wmma::fragment<wmma::matrix_b, 16, 16, 16, __nv_bfloat16,
                               wmma::col_major> fbh, fbl;
                wmma::load_matrix_sync(fbh, sBh + j * 16 * S2PAD + kk, S2PAD);
                wmma::load_matrix_sync(fbl, sBl + j * 16 * S2PAD + kk, S2PAD);
                wmma::mma_sync(acc[j], fah, fbh, acc[j]);
                wmma::mma_sync(acc[j], fal, fbh, acc[j]);
                wmma::mma_sync(acc[j], fah, fbl, acc[j]);
            }
        }
        __syncthreads();
    }

    float* sC = (float*)dsm;
#pragma unroll
    for (int j = 0; j < 6; j++)
        wmma::store_matrix_sync(sC + (wid * 16) * 96 + j * 16, acc[j], 96,
                                wmma::mem_row_major);
    __syncthreads();

#pragma unroll
    for (int it = 0; it < 12; it++) {
        int idx = tid + it * 256;
        int r = idx / 24;
        int c4 = idx % 24;
        float4 v = ((const float4*)sC)[idx];
        *(float4*)(C + (size_t)(bm + r) * E_ + c4 * 4) = v;
    }
}

// Deterministic fixed-order reduce of 4 split-K partials.
// Also emits dlr (= dbc[:, 0:64]) as bf16 hi/lo for the delta HMMA GEMM.
__global__ __launch_bounds__(256) void dbcred_kernel(
    const float* __restrict__ P, float* __restrict__ C,
    __nv_bfloat16* __restrict__ dlrh, __nv_bfloat16* __restrict__ dlrl) {
    int i = blockIdx.x * 256 + threadIdx.x;  // float4 index < 98304
    const size_t stride = (size_t)ML_ * E_ / 4;
    const float4* p = (const float4*)P;
    float4 a = p[i];
    float4 b = p[stride + i];
    float4 c = p[2 * stride + i];
    float4 d = p[3 * stride + i];
    float4 o = make_float4(((a.x + b.x) + (c.x + d.x)),
                           ((a.y + b.y) + (c.y + d.y)),
                           ((a.z + b.z) + (c.z + d.z)),
                           ((a.w + b.w) + (c.w + d.w)));
    ((float4*)C)[i] = o;
    int r = i / 24;
    int c4 = i % 24;
    if (c4 < 16) {  // cols < 64 -> dlr path
        float vv[4] = {o.x, o.y, o.z, o.w};
        __nv_bfloat16 h[4], l[4];
#pragma unroll
        for (int j = 0; j < 4; j++) {
            h[j] = __float2bfloat16(vv[j]);
            l[j] = __float2bfloat16(vv[j] - __bfloat162float(h[j]));
        }
        ((uint2*)dlrh)[r * 16 + c4] = *(uint2*)h;
        ((uint2*)dlrl)[r * 16 + c4] = *(uint2*)l;
    }
}

// ---------------------------------------------------------------------------
// delta HMMA GEMM: delta[4096,1024] = softplus(dlr @ W_dt^T + b_dt)
// bf16 3-term, K=64 single-shot. CTA 128x128, 8 warps (4x2).
// __launch_bounds__(256,2); inner loop keeps live frags at 112 regs.
// ---------------------------------------------------------------------------
#define DT_TILE (128 * HPAD * 2)   // 18432 bytes (K=64 + pad rows)
#define DSMEM (4 * DT_TILE)        // 73728 bytes (>= 64KB epilogue staging)

__global__ __launch_bounds__(256, 2) void gemm_delta_kernel(
    const __nv_bfloat16* __restrict__ Ah, const __nv_bfloat16* __restrict__ Al,
    const __nv_bfloat16* __restrict__ Bh, const __nv_bfloat16* __restrict__ Bl,
    const float* __restrict__ bias, float* __restrict__ C) {
    extern __shared__ char dsm[];
    int tid = threadIdx.x;
    int wid = tid >> 5;
    int wm = wid >> 1;
    int wn = wid & 1;
    int bm = blockIdx.y * 128;
    int bn = blockIdx.x * 128;

    // Load all four 128x64 bf16 tiles (Ah, Al, Bh, Bl)
    {
        uint32_t sb = smem_u32(dsm);
#pragma unroll
        for (int j = 0; j < 8; j++) {
            int idx = tid + j * 256;   // 0..2047
            int r = idx >> 4;          // 0..127
            int g = idx & 15;          // groups of 4 halves
            uint32_t so = (uint32_t)(r * (HPAD * 2) + g * 8);
            size_t ao = (size_t)(bm + r) * R_ + g * 4;
            size_t bo = (size_t)(bn + r) * R_ + g * 4;
            cp_async8(sb + so, Ah + ao);
            cp_async8(sb + DT_TILE + so, Al + ao);
            cp_async8(sb + 2 * DT_TILE + so, Bh + bo);
            cp_async8(sb + 3 * DT_TILE + so, Bl + bo);
        }
        cp_commit();
        cp_wait<0>();
        __syncthreads();
    }

    const __nv_bfloat16* sAh = (const __nv_bfloat16*)dsm;
    const __nv_bfloat16* sAl = (const __nv_bfloat16*)(dsm + DT_TILE);
    const __nv_bfloat16* sBh = (const __nv_bfloat16*)(dsm + 2 * DT_TILE);
    const __nv_bfloat16* sBl = (const __nv_bfloat16*)(dsm + 3 * DT_TILE);

    wmma::fragment<wmma::accumulator, 16, 16, 16, float> acc[2][4];
#pragma unroll
    for (int i = 0; i < 2; i++)
#pragma unroll
        for (int j = 0; j < 4; j++) wmma::fill_fragment(acc[i][j], 0.0f);

#pragma unroll
    for (int kk = 0; kk < 64; kk += 16) {
        wmma::fragment<wmma::matrix_a, 16, 16, 16, __nv_bfloat16,
                       wmma::row_major> fah[2], fal[2];
#pragma unroll
        for (int i = 0; i < 2; i++) {
            int r0 = wm * 32 + i * 16;
            wmma::load_matrix_sync(fah[i], sAh + r0 * HPAD + kk, HPAD);
            wmma::load_matrix_sync(fal[i], sAl + r0 * HPAD + kk, HPAD);
        }
#pragma unroll
        for (int j = 0; j < 4; j++) {
            int c0 = wn * 64 + j * 16;
            wmma::fragment<wmma::matrix_b, 16, 16, 16, __nv_bfloat16,
                           wmma::col_major> fbh, fbl;
            wmma::load_matrix_sync(fbh, sBh + c0 * HPAD + kk, HPAD);
            wmma::load_matrix_sync(fbl, sBl + c0 * HPAD + kk, HPAD);
#pragma unroll
            for (int i = 0; i < 2; i++) {
                wmma::mma_sync(acc[i][j], fah[i], fbh, acc[i][j]);
                wmma::mma_sync(acc[i][j], fal[i], fbh, acc[i][j]);
                wmma::mma_sync(acc[i][j], fah[i], fbl, acc[i][j]);
            }
        }
    }
    __syncthreads();

    float* sC = (float*)dsm;
#pragma unroll
    for (int i = 0; i < 2; i++)
#pragma unroll
        for (int j = 0; j < 4; j++)
            wmma::store_matrix_sync(sC + (wm * 32 + i * 16) * 128 +
                                        (wn * 64 + j * 16),
                                    acc[i][j], 128, wmma::mem_row_major);
    __syncthreads();

#pragma unroll
    for (int it = 0; it < 16; it++) {
        int idx = tid + it * 256;
        int r = idx >> 5;
        int c4 = idx & 31;
        float4 v = ((const float4*)(sC + r * 128))[c4];
        size_t row = bm + r;
        size_t col = bn + c4 * 4;
        const float4 bv = *(const float4*)(bias + col);
        float4 o = make_float4(softplus_f(v.x + bv.x), softplus_f(v.y + bv.y),
                               softplus_f(v.z + bv.z), softplus_f(v.w + bv.w));
        *(float4*)(C + row * D_ + col) = o;
    }
}

// ---------------------------------------------------------------------------
// ln1 mega-fused. Block ranges:
//  [0, ML_)                      : softplus(ln(x)) -> fp32 + bf16 hi/lo
//  [ML_, +96)                    : W_dbc -> bf16 hi/lo
//  [ML_+96, +4096)               : W_fc -> fp16
//  [ML_+4192, +4096)             : W_proj -> fp16
//  [ML_+8288, +64)               : W_dt -> bf16 hi/lo
// ---------------------------------------------------------------------------
#define LN1_GRID (ML_ + 96 + 4096 + 4096 + 64)

__global__ __launch_bounds__(256) void ln1_mega_kernel(
    const float* __restrict__ x, const float* __restrict__ w,
    const float* __restrict__ W_dbc, const float* __restrict__ W_fc,
    const float* __restrict__ W_proj, const float* __restrict__ W_dt,
    float* __restrict__ out, __nv_bfloat16* __restrict__ oh,
    __nv_bfloat16* __restrict__ ol,
    __nv_bfloat16* __restrict__ wdh, __nv_bfloat16* __restrict__ wdl,
    __half* __restrict__ wfcf, __half* __restrict__ wprf,
    __nv_bfloat16* __restrict__ wdth, __nv_bfloat16* __restrict__ wdtl) {
    __shared__ float red[8];
    int bid = blockIdx.x;
    int t = threadIdx.x;

    if (bid >= ML_) {
        int r = bid - ML_;
        if (r < 96) {  // W_dbc bf16 hi/lo split
            int i = r * 256 + t;
            float4 v = ((const float4*)W_dbc)[i];
            float vv[4] = {v.x, v.y, v.z, v.w};
            __nv_bfloat16 h[4], l[4];
#pragma unroll
            for (int j = 0; j < 4; j++) {
                h[j] = __float2bfloat16(vv[j]);
                l[j] = __float2bfloat16(vv[j] - __bfloat162float(h[j]));
            }
            ((uint2*)wdh)[i] = *(uint2*)h;
            ((uint2*)wdl)[i] = *(uint2*)l;
        } else if (r < 96 + 4096) {  // W_fc -> fp16
            int i = (r - 96) * 256 + t;
            float4 v = ((const float4*)W_fc)[i];
            __half h[4] = {__float2half(v.x), __float2half(v.y),
                           __float2half(v.z), __float2half(v.w)};
            ((uint2*)wfcf)[i] = *(uint2*)h;
        } else if (r < 96 + 8192) {  // W_proj -> fp16
            int i = (r - 96 - 4096) * 256 + t;
            float4 v = ((const float4*)W_proj)[i];
            __half h[4] = {__float2half(v.x), __float2half(v.y),
                           __float2half(v.z), __float2half(v.w)};
            ((uint2*)wprf)[i] = *(uint2*)h;
        } else {  // W_dt bf16 hi/lo split (16384 float4)
            int i = (r - 96 - 8192) * 256 + t;
            float4 v = ((const float4*)W_dt)[i];
            float vv[4] = {v.x, v.y, v.z, v.w};
            __nv_bfloat16 h[4], l[4];
#pragma unroll
            for (int j = 0; j < 4; j++) {
                h[j] = __float2bfloat16(vv[j]);
                l[j] = __float2bfloat16(vv[j] - __bfloat162float(h[j]));
            }
            ((uint2*)wdth)[i] = *(uint2*)h;
            ((uint2*)wdtl)[i] = *(uint2*)l;
        }
        return;
    }

    int row = bid;
    const float4* xr = (const float4*)(x + (size_t)row * D_);
    float4 v = xr[t];

    float s = v.x + v.y + v.z + v.w;
#pragma unroll
    for (int m = 16; m > 0; m >>= 1) s += __shfl_xor_sync(0xffffffffu, s, m);
    if ((t & 31) == 0) red[t >> 5] = s;
    __syncthreads();
    float tot = 0.0f;
#pragma unroll
    for (int i = 0; i < 8; i++) tot += red[i];
    float mu = tot * (1.0f / D_);

    float cx = v.x - mu, cy = v.y - mu, cz = v.z - mu, cw = v.w - mu;
    float s2 = cx * cx + cy * cy + cz * cz + cw * cw;
#pragma unroll
    for (int m = 16; m > 0; m >>= 1) s2 += __shfl_xor_sync(0xffffffffu, s2, m);
    __syncthreads();
    if ((t & 31) == 0) red[t >> 5] = s2;
    __syncthreads();
    float tot2 = 0.0f;
#pragma unroll
    for (int i = 0; i < 8; i++) tot2 += red[i];
    float rs = rsqrtf(tot2 * (1.0f / D_) + 1e-5f);

    float4 wv = ((const float4*)w)[t];
    float o[4];
    o[0] = softplus_f(cx * rs * wv.x);
    o[1] = softplus_f(cy * rs * wv.y);
    o[2] = softplus_f(cz * rs * wv.z);
    o[3] = softplus_f(cw * rs * wv.w);
    ((float4*)(out + (size_t)row * D_))[t] = make_float4(o[0], o[1], o[2], o[3]);

    __nv_bfloat16 h[4], l[4];
#pragma unroll
    for (int j = 0; j < 4; j++) {
        h[j] = __float2bfloat16(o[j]);
        l[j] = __float2bfloat16(o[j] - __bfloat162float(h[j]));
    }
    ((uint2*)(oh + (size_t)row * D_))[t] = *(uint2*)h;
    ((uint2*)(ol + (size_t)row * D_))[t] = *(uint2*)l;
}

// ---------------------------------------------------------------------------
// ln2: ln(h) -> fp16 single
// ---------------------------------------------------------------------------
__global__ __launch_bounds__(256) void ln2_kernel(const float* __restrict__ x,
                                                  const float* __restrict__ w,
                                                  __half* __restrict__ o16) {
    int row = blockIdx.x;
    int t = threadIdx.x;
    __shared__ float red[8];

    const float4* xr = (const float4*)(x + (size_t)row * D_);
    float4 v = xr[t];

    float s = v.x + v.y + v.z + v.w;
#pragma unroll
    for (int m = 16; m > 0; m >>= 1) s += __shfl_xor_sync(0xffffffffu, s, m);
    if ((t & 31) == 0) red[t >> 5] = s;
    __syncthreads();
    float tot = 0.0f;
#pragma unroll
    for (int i = 0; i < 8; i++) tot += red[i];
    float mu = tot * (1.0f / D_);

    float cx = v.x - mu, cy = v.y - mu, cz = v.z - mu, cw = v.w - mu;
    float s2 = cx * cx + cy * cy + cz * cz + cw * cw;
#pragma unroll
    for (int m = 16; m > 0; m >>= 1) s2 += __shfl_xor_sync(0xffffffffu, s2, m);
    __syncthreads();
    if ((t & 31) == 0) red[t >> 5] = s2;
    __syncthreads();
    float tot2 = 0.0f;
#pragma unroll
    for (int i = 0; i < 8; i++) tot2 += red[i];
    float rs = rsqrtf(tot2 * (1.0f / D_) + 1e-5f);

    float4 wv = ((const float4*)w)[t];
    __half h[4];
    h[0] = __float2half(cx * rs * wv.x);
    h[1] = __float2half(cy * rs * wv.y);
    h[2] = __float2half(cz * rs * wv.z);
    h[3] = __float2half(cw * rs * wv.w);
    ((uint2*)(o16 + (size_t)row * D_))[t] = *(uint2*)h;
}

// ---------------------------------------------------------------------------
// Selective scan v3.1: block-local chunked parallel scan (unchanged)
// ---------------------------------------------------------------------------
#define NCH 16
#define CHL 64
#define SUBL 32

#define SC3_BC 0
#define SC3_PA 65536
#define SC3_ST 98304
#define SC3_SMEM 131072

__global__ __launch_bounds__(512) void scan3_kernel(
    const float* __restrict__ h0, const float* __restrict__ delta,
    const float* __restrict__ dbc, const float* __restrict__ A_log,
    const float* __restrict__ Dp, float* __restrict__ hout) {
    extern __shared__ char dsm[];
    float* sBC = (float*)(dsm + SC3_BC);
    float* sPA = (float*)(dsm + SC3_PA);
    float* sST = (float*)(dsm + SC3_ST);

    int tid = threadIdx.x;
    int lane = tid & 31;
    int w = tid >> 5;
    int d = blockIdx.x * 32 + lane;
    int b = blockIdx.y;

    float negA0 = -__expf(A_log[d * NS_]);
    float eps[16];
#pragma unroll
    for (int n = 0; n < 16; n++)
        eps[n] = -__expf(A_log[d * NS_ + n]) - (float)(n + 1) * negA0;
    float dp = Dp[d];

    size_t xbase = ((size_t)b * L_ + (size_t)w * CHL) * D_ + d;
    size_t ebase = ((size_t)b * L_ + (size_t)w * CHL) * E_ + R_ + lane;

    float st[16];
#pragma unroll
    for (int n = 0; n < 16; n++) st[n] = 0.0f;
    float sdelta = 0.0f;

    // Phase A: local scan from zero state + sum of deltas
    {
        float pdl[4], pxv[4];
#pragma unroll
        for (int i = 0; i < 4; i++) {
            pdl[i] = delta[xbase + (size_t)i * D_];
            pxv[i] = h0[xbase + (size_t)i * D_];
        }
#pragma unroll
        for (int sub = 0; sub < CHL / SUBL; sub++) {
            float* bcw = sBC + (w * SUBL) * 32;
#pragma unroll 8
            for (int l = 0; l < SUBL; l++)
                bcw[l * 32 + lane] =
                    dbc[ebase + (size_t)(sub * SUBL + l) * E_];
            __syncwarp();

#pragma unroll 4
            for (int l = 0; l < SUBL; l++) {
                int gl = sub * SUBL + l;
                float dv = pdl[gl & 3];
                float xv = pxv[gl & 3];
                int lf = gl + 4;
                if (lf < CHL) {
                    pdl[gl & 3] = delta[xbase + (size_t)lf * D_];
                    pxv[gl & 3] = h0[xbase + (size_t)lf * D_];
                }

                float Bv[16];
                *(float4*)&Bv[0]  = *(const float4*)&bcw[l * 32 + 0];
                *(float4*)&Bv[4]  = *(const float4*)&bcw[l * 32 + 4];
                *(float4*)&Bv[8]  = *(const float4*)&bcw[l * 32 + 8];
                *(float4*)&Bv[12] = *(const float4*)&bcw[l * 32 + 12];

                float p = __expf(dv * negA0);
                float p2 = p * p, p4 = p2 * p2, p8 = p4 * p4;
                float pw[16];
                pw[0] = p;          pw[1] = p2;         pw[2] = p2 * p;
                pw[3] = p4;         pw[4] = p4 * p;     pw[5] = p4 * p2;
                pw[6] = p4 * pw[2]; pw[7] = p8;
                pw[8] = p8 * p;     pw[9] = p8 * p2;    pw[10] = p8 * pw[2];
                pw[11] = p8 * p4;   pw[12] = p8 * pw[4]; pw[13] = p8 * pw[5];
                pw[14] = p8 * pw[6]; pw[15] = p8 * p8;

                sdelta += dv;
                float dx = dv * xv;
#pragma unroll
                for (int n = 0; n < 16; n++) {
                    float a = pw[n] * fmaf(dv, eps[n], 1.0f);
                    st[n] = fmaf(a, st[n], dx * Bv[n]);
                }
            }
            __syncwarp();
        }
    }

    // publish chunk summaries
#pragma unroll
    for (int n = 0; n < 16; n++) {
        float negAn = fmaf((float)(n + 1), negA0, eps[n]);
        sPA[(w * NS_ + n) * 32 + lane] = __expf(negAn * sdelta);
        sST[(w * NS_ + n) * 32 + lane] = st[n];
    }
    __syncthreads();

    // Phase B: block combine
    {
        int cd = tid & 31;
        int cn = tid >> 5;
        float hacc = 0.0f;
#pragma unroll
        for (int wc = 0; wc < NCH; wc++) {
            int off = (wc * NS_ + cn) * 32 + cd;
            float pav = sPA[off];
            float stv = sST[off];
            sPA[off] = hacc;
            hacc = fmaf(pav, hacc, stv);
        }
    }
    __syncthreads();

    // Phase C: re-scan with correct init, emit output
#pragma unroll
    for (int n = 0; n < 16; n++) st[n] = sPA[(w * NS_ + n) * 32 + lane];

    {
        float pdl[4], pxv[4];
#pragma unroll
        for (int i = 0; i < 4; i++) {
            pdl[i] = delta[xbase + (size_t)i * D_];
            pxv[i] = h0[xbase + (size_t)i * D_];
        }
#pragma unroll
        for (int sub = 0; sub < CHL / SUBL; sub++) {
            float* bcw = sBC + (w * SUBL) * 32;
#pragma unroll 8
            for (int l = 0; l < SUBL; l++)
                bcw[l * 32 + lane] =
                    dbc[ebase + (size_t)(sub * SUBL + l) * E_];
            __syncwarp();

#pragma unroll 4
            for (int l = 0; l < SUBL; l++) {
                int gl = sub * SUBL + l;
                float dv = pdl[gl & 3];
                float xv = pxv[gl & 3];
                int lf = gl + 4;
                if (lf < CHL) {
                    pdl[gl & 3] = delta[xbase + (size_t)lf * D_];
                    pxv[gl & 3] = h0[xbase + (size_t)lf * D_];
                }

                float Bv[16], Cv[16];
                *(float4*)&Bv[0]  = *(const float4*)&bcw[l * 32 + 0];
                *(float4*)&Bv[4]  = *(const float4*)&bcw[l * 32 + 4];
                *(float4*)&Bv[8]  = *(const float4*)&bcw[l * 32 + 8];
                *(float4*)&Bv[12] = *(const float4*)&bcw[l * 32 + 12];
                *(float4*)&Cv[0]  = *(const float4*)&bcw[l * 32 + 16];
                *(float4*)&Cv[4]  = *(const float4*)&bcw[l * 32 + 20];
                *(float4*)&Cv[8]  = *(const float4*)&bcw[l * 32 + 24];
                *(float4*)&Cv[12] = *(const float4*)&bcw[l * 32 + 28];

                float p = __expf(dv * negA0);
                float p2 = p * p, p4 = p2 * p2, p8 = p4 * p4;
                float pw[16];
                pw[0] = p;          pw[1] = p2;         pw[2] = p2 * p;
                pw[3] = p4;         pw[4] = p4 * p;     pw[5] = p4 * p2;
                pw[6] = p4 * pw[2]; pw[7] = p8;
                pw[8] = p8 * p;     pw[9] = p8 * p2;    pw[10] = p8 * pw[2];
                pw[11] = p8 * p4;   pw[12] = p8 * pw[4]; pw[13] = p8 * pw[5];
                pw[14] = p8 * pw[6]; pw[15] = p8 * p8;

                float dx = dv * xv;
                float y0 = 0.f, y1 = 0.f, y2 = 0.f, y3 = 0.f;
#pragma unroll
                for (int n = 0; n < 16; n++) {
                    float a = pw[n] * fmaf(dv, eps[n], 1.0f);
                    st[n] = fmaf(a, st[n], dx * Bv[n]);
                    float yv = st[n] * Cv[n];
                    if ((n & 3) == 0) y0 += yv;
                    else if ((n & 3) == 1) y1 += yv;
                    else if ((n & 3) == 2) y2 += yv;
                    else y3 += yv;
                }
                float y = (y0 + y1) + (y2 + y3);
                hout[xbase + (size_t)gl * D_] = fmaf(xv, dp, xv + y);
            }
            __syncwarp();
        }
    }
}

// ---------------------------------------------------------------------------
// Launch
// ---------------------------------------------------------------------------
extern "C" void kernel_launch(void* const* d_in, const int* in_sizes, int n_in,
                              void* d_out, int out_size) {
    const float* x      = (const float*)d_in[0];
    const float* ln1_w  = (const float*)d_in[1];
    const float* ln2_w  = (const float*)d_in[2];
    const float* W_dbc  = (const float*)d_in[3];
    const float* W_dt   = (const float*)d_in[4];
    const float* b_dt   = (const float*)d_in[5];
    const float* A_log  = (const float*)d_in[6];
    const float* Dp     = (const float*)d_in[7];
    const float* W_fc   = (const float*)d_in[8];
    const float* W_proj = (const float*)d_in[9];
    float* out = (float*)d_out;

    float *h0, *dbc, *dbcp, *delta, *h;
    __nv_bfloat16 *h0h, *h0l, *wdbh, *wdbl, *dlrh, *dlrl, *wdth, *wdtl;
    __half *m0f, *fcf, *wfcf, *wprf;
    cudaGetSymbolAddress((void**)&h0, g_h0);
    cudaGetSymbolAddress((void**)&dbc, g_dbc);
    cudaGetSymbolAddress((void**)&dbcp, g_dbcp);
    cudaGetSymbolAddress((void**)&delta, g_delta);
    cudaGetSymbolAddress((void**)&h, g_h);
    cudaGetSymbolAddress((void**)&h0h, g_h0h);
    cudaGetSymbolAddress((void**)&h0l, g_h0l);
    cudaGetSymbolAddress((void**)&wdbh, g_wdbh);
    cudaGetSymbolAddress((void**)&wdbl, g_wdbl);
    cudaGetSymbolAddress((void**)&dlrh, g_dlrh);
    cudaGetSymbolAddress((void**)&dlrl, g_dlrl);
    cudaGetSymbolAddress((void**)&wdth, g_wdth);
    cudaGetSymbolAddress((void**)&wdtl, g_wdtl);
    cudaGetSymbolAddress((void**)&m0f, g_m0f);
    cudaGetSymbolAddress((void**)&fcf, g_fcf);
    cudaGetSymbolAddress((void**)&wfcf, g_wfcf);
    cudaGetSymbolAddress((void**)&wprf, g_wprf);

    cudaFuncSetAttribute(gemm_hmma_kernel<1>,
                         cudaFuncAttributeMaxDynamicSharedMemorySize,
                         HSMEM_TOTAL);
    cudaFuncSetAttribute(gemm_hmma_kernel<2>,
                         cudaFuncAttributeMaxDynamicSharedMemorySize,
                         HSMEM_TOTAL);
    cudaFuncSetAttribute(gemm_dbc2_kernel,
                         cudaFuncAttributeMaxDynamicSharedMemorySize, S2TOT);
    cudaFuncSetAttribute(gemm_delta_kernel,
                         cudaFuncAttributeMaxDynamicSharedMemorySize, DSMEM);
    cudaFuncSetAttribute(scan3_kernel,
                         cudaFuncAttributeMaxDynamicSharedMemorySize,
                         SC3_SMEM);

    // 1. softplus(ln1(x)) + all weight converts/splits
    ln1_mega_kernel<<<LN1_GRID, 256>>>(x, ln1_w, W_dbc, W_fc, W_proj, W_dt,
                                       h0, h0h, h0l, wdbh, wdbl, wfcf, wprf,
                                       wdth, wdtl);

    // 2. dbc partials: split-K x4 (M=4096, N=96, K=1024) [bf16 3-term WMMA]
    gemm_dbc2_kernel<<<dim3(ML_ / 128, 4), 256, S2TOT>>>(h0h, h0l, wdbh, wdbl,
                                                         dbcp);

    // 3. dbc = sum of partials (+ dlr bf16 hi/lo emit)
    dbcred_kernel<<<ML_ * E_ / 1024, 256>>>(dbcp, dbc, dlrh, dlrl);

    // 4. delta = softplus(dlr @ W_dt^T + b_dt)  [bf16 3-term HMMA]
    gemm_delta_kernel<<<dim3(D_ / 128, ML_ / 128), 256, DSMEM>>>(
        dlrh, dlrl, wdth, wdtl, b_dt, delta);

    // 5. h = h0 + ssm(h0)   [chunked block-parallel scan]
    scan3_kernel<<<dim3(D_ / 32, B_), 512, SC3_SMEM>>>(h0, delta, dbc, A_log,
                                                       Dp, h);

    // 6. m0 = ln2(h) -> fp16
    ln2_kernel<<<ML_, 256>>>(h, ln2_w, m0f);

    // 7. fc = gelu(m0 @ W_fc^T) -> fp16   (M=4096, N=4096, K=1024)
    gemm_hmma_kernel<1><<<dim3(F_ / 128, ML_ / 128), 256, HSMEM_TOTAL>>>(
        m0f, wfcf, D_, fcf, nullptr, nullptr, F_);

    // 8. out = h + fc @ W_proj^T   (M=4096, N=1024, K=4096)
    gemm_hmma_kernel<2><<<dim3(D_ / 128, ML_ / 128), 256, HSMEM_TOTAL>>>(
        fcf, wprf, F_, nullptr, out, h, D_);
}